// round 5
// baseline (speedup 1.0000x reference)
#include <cuda_runtime.h>
#include <cstdint>

#define BATCH 32
#define DIM   256
#define HW    56
#define SP    (HW*HW)        // 3136
#define PW    7
#define PP    49
#define DD    3
#define N1    8
#define N2    8
#define NWIN  64
#define HEADS 8
#define DH    32
#define INNER 256
#define QKV_N 768
#define M_TOTAL (BATCH*NWIN*PP)   // 100352

__device__ float g_qkv[(size_t)M_TOTAL * QKV_N];   // ~308 MB
__device__ float g_att[(size_t)M_TOTAL * INNER];   // ~103 MB

__device__ __forceinline__ int row_to_off(int r) {
    int bi  = r / (NWIN * PP);
    int rem = r % (NWIN * PP);
    int w   = rem / PP;
    int t   = rem % PP;
    int n1i = w / N2, n2i = w % N2;
    int py  = t / PW, px  = t % PW;
    int hh  = (n1i * PW + py + DD) % HW;
    int ww  = (n2i * PW + px + DD) % HW;
    return bi * DIM * SP + hh * HW + ww;
}

__device__ __forceinline__ void cp4(void* dst, const void* src) {
    uint32_t d = (uint32_t)__cvta_generic_to_shared(dst);
    asm volatile("cp.async.ca.shared.global [%0], [%1], 4;" :: "r"(d), "l"(src));
}
#define CP_COMMIT() asm volatile("cp.async.commit_group;")
#define CP_WAIT(n)  asm volatile("cp.async.wait_group %0;" :: "n"(n))

// ---------------------------------------------------------------------------
// Kernel 1: qkv = window(roll(x)) @ w_qkv — 128x128 tile, 8x8 micro,
// cp.async double-buffered, 2 CTAs/SM
// ---------------------------------------------------------------------------
__global__ void __launch_bounds__(256, 2) qkv_gemm(const float* __restrict__ x,
                                                   const float* __restrict__ wqkv) {
    __shared__ float As[2][16][128];
    __shared__ float Bs[2][16][128];
    __shared__ int   rowoff[128];

    const int m0  = blockIdx.x * 128;
    const int n0  = blockIdx.y * 128;
    const int tid = threadIdx.x;

    if (tid < 128) rowoff[tid] = row_to_off(m0 + tid);
    __syncthreads();

    const int lm  = tid & 127;
    const int lk0 = tid >> 7;      // 0..1
    const int tr  = (tid >> 4) * 8;
    const int tc  = (tid & 15) * 8;

    float acc[8][8] = {};

    // prologue: stage chunk 0 into buf 0
    #pragma unroll
    for (int i = 0; i < 8; i++) {
        int kk = lk0 + 2 * i;
        cp4(&As[0][kk][lm], &x[rowoff[lm] + kk * SP]);
        cp4(&Bs[0][kk][lm], &wqkv[kk * QKV_N + n0 + lm]);
    }
    CP_COMMIT();

    #pragma unroll
    for (int k0 = 0; k0 < DIM; k0 += 16) {
        const int cur = (k0 >> 4) & 1;
        const int nxt = cur ^ 1;
        if (k0 + 16 < DIM) {
            #pragma unroll
            for (int i = 0; i < 8; i++) {
                int kk = lk0 + 2 * i;
                cp4(&As[nxt][kk][lm], &x[rowoff[lm] + (k0 + 16 + kk) * SP]);
                cp4(&Bs[nxt][kk][lm], &wqkv[(k0 + 16 + kk) * QKV_N + n0 + lm]);
            }
            CP_COMMIT();
            CP_WAIT(1);
        } else {
            CP_WAIT(0);
        }
        __syncthreads();
        #pragma unroll
        for (int k = 0; k < 16; k++) {
            float a[8], b[8];
            *(float4*)(a)     = *(const float4*)&As[cur][k][tr];
            *(float4*)(a + 4) = *(const float4*)&As[cur][k][tr + 4];
            *(float4*)(b)     = *(const float4*)&Bs[cur][k][tc];
            *(float4*)(b + 4) = *(const float4*)&Bs[cur][k][tc + 4];
            #pragma unroll
            for (int i = 0; i < 8; i++)
                #pragma unroll
                for (int j = 0; j < 8; j++)
                    acc[i][j] += a[i] * b[j];
        }
        __syncthreads();
    }

    #pragma unroll
    for (int i = 0; i < 8; i++) {
        float* dst = &g_qkv[(size_t)(m0 + tr + i) * QKV_N + n0 + tc];
        *(float4*)(dst)     = make_float4(acc[i][0], acc[i][1], acc[i][2], acc[i][3]);
        *(float4*)(dst + 4) = make_float4(acc[i][4], acc[i][5], acc[i][6], acc[i][7]);
    }
}

// ---------------------------------------------------------------------------
// Kernel 2: per (b, window, head) attention. Parallel chunked softmax.
// ---------------------------------------------------------------------------
__global__ void __launch_bounds__(256) attn_kernel(const float* __restrict__ pos,
                                                   float* __restrict__ attn_out) {
    const int bid  = blockIdx.x;                // bi*NWIN*HEADS + w*HEADS + head
    const int head = bid % HEADS;
    const int bw   = bid / HEADS;
    const int w    = bw % NWIN;
    const int bi   = bw / NWIN;
    const int tid  = threadIdx.x;

    __shared__ float q[PP][DH];
    __shared__ float kT[DH][52];      // transposed K, conflict-free over j
    __shared__ float v[PP][DH];
    __shared__ float dots[PP][53];    // odd stride
    __shared__ float poss[169];
    __shared__ float cpart[PP][13];   // per-(row, j-chunk) partials
    __shared__ float rowm[PP], rowinv[PP];

    const float* base = g_qkv + (size_t)(bi * NWIN + w) * PP * QKV_N + head * DH;
    for (int idx = tid; idx < PP * 8; idx += 256) {
        int t = idx >> 3, c = idx & 7;
        const float* rowp = base + (size_t)t * QKV_N + c * 4;
        float4 qf = *(const float4*)(rowp);
        float4 kf = *(const float4*)(rowp + INNER);
        float4 vf = *(const float4*)(rowp + 2 * INNER);
        *(float4*)&q[t][c * 4] = qf;
        *(float4*)&v[t][c * 4] = vf;
        int d = c * 4;
        kT[d][t] = kf.x; kT[d + 1][t] = kf.y; kT[d + 2][t] = kf.z; kT[d + 3][t] = kf.w;
    }
    if (tid < DH) { kT[tid][49] = 0.f; kT[tid][50] = 0.f; kT[tid][51] = 0.f; }
    for (int idx = tid; idx < 169; idx += 256) poss[idx] = pos[idx];
    __syncthreads();

    const bool m_ul = (w >= NWIN - N2);                                          // 56..63
    const bool m_lr = (w >= NWIN - N1 - 1) && ((w - (NWIN - N1 - 1)) % N1 == 0); // {55,63}
    const float NEG = -1e30f;
    const float scale = 0.17677669529663687f;  // 1/sqrt(32)

    // Pass 1: dots (float4 over j) + per-chunk max
    for (int idx = tid; idx < PP * 13; idx += 256) {
        int i = idx / 13, jc = idx % 13, j0 = jc * 4;
        float4 s = make_float4(0.f, 0.f, 0.f, 0.f);
        #pragma unroll
        for (int d = 0; d < DH; d++) {
            float qv = q[i][d];
            float4 kf = *(const float4*)&kT[d][j0];
            s.x += qv * kf.x; s.y += qv * kf.y; s.z += qv * kf.z; s.w += qv * kf.w;
        }
        int iy = i / PW, ix = i % PW;
        float sv[4] = {s.x, s.y, s.z, s.w};
        float cm = -3.4e38f;
        #pragma unroll
        for (int jj = 0; jj < 4; jj++) {
            int j = j0 + jj;
            if (j < PP) {
                int jy = j / PW, jx = j % PW;
                float val = sv[jj] * scale + poss[(jy - iy + 6) * 13 + (jx - ix + 6)];
                if (m_ul && ((iy >= 4) != (jy >= 4))) val = NEG;
                if (m_lr && ((ix >= 4) != (jx >= 4))) val = NEG;
                dots[i][j] = val;
                cm = fmaxf(cm, val);
            }
        }
        cpart[i][jc] = cm;
    }
    __syncthreads();

    if (tid < PP) {
        float m = cpart[tid][0];
        #pragma unroll
        for (int c = 1; c < 13; c++) m = fmaxf(m, cpart[tid][c]);
        rowm[tid] = m;
    }
    __syncthreads();

    // Pass 2: exp + per-chunk sum
    for (int idx = tid; idx < PP * 13; idx += 256) {
        int i = idx / 13, jc = idx % 13, j0 = jc * 4;
        float m = rowm[i];
        float ps = 0.f;
        #pragma unroll
        for (int jj = 0; jj < 4; jj++) {
            int j = j0 + jj;
            if (j < PP) {
                float e = __expf(dots[i][j] - m);
                dots[i][j] = e;
                ps += e;
            }
        }
        cpart[i][jc] = ps;
    }
    __syncthreads();

    if (tid < PP) {
        float s = 0.f;
        #pragma unroll
        for (int c = 0; c < 13; c++) s += cpart[tid][c];
        rowinv[tid] = 1.0f / s;
    }
    __syncthreads();

    // attn output (normalized on the fly)
    float* ao = attn_out + (size_t)bid * (PP * PP);
    for (int idx = tid; idx < PP * PP; idx += 256) {
        int i = idx / PP, j = idx % PP;
        ao[idx] = dots[i][j] * rowinv[i];
    }

    // attn @ v (normalize at the end)
    float* ob = g_att + (size_t)(bi * NWIN + w) * PP * INNER + head * DH;
    for (int idx = tid; idx < PP * DH; idx += 256) {
        int i = idx / DH, d = idx % DH;
        float s = 0.f;
        #pragma unroll
        for (int j = 0; j < PP; j++) s += dots[i][j] * v[j][d];
        ob[(size_t)i * INNER + d] = s * rowinv[i];
    }
}

// ---------------------------------------------------------------------------
// Kernel 3: out = g_att @ w_out + b_out, scattered inverse window + roll
// ---------------------------------------------------------------------------
__global__ void __launch_bounds__(256, 2) out_gemm(const float* __restrict__ wout,
                                                   const float* __restrict__ bout,
                                                   float* __restrict__ out) {
    __shared__ float As[2][16][128];
    __shared__ float Bs[2][16][128];
    __shared__ int   rowoff[128];

    const int m0  = blockIdx.x * 128;
    const int n0  = blockIdx.y * 128;
    const int tid = threadIdx.x;

    if (tid < 128) rowoff[tid] = row_to_off(m0 + tid);
    __syncthreads();

    const int lm  = tid & 127;
    const int lk0 = tid >> 7;
    const int tr  = (tid >> 4) * 8;
    const int tc  = (tid & 15) * 8;

    float acc[8][8] = {};

    #pragma unroll
    for (int i = 0; i < 8; i++) {
        int kk = lk0 + 2 * i;
        cp4(&As[0][kk][lm], &g_att[(size_t)(m0 + lm) * INNER + kk]);
        cp4(&Bs[0][kk][lm], &wout[kk * DIM + n0 + lm]);
    }
    CP_COMMIT();

    #pragma unroll
    for (int k0 = 0; k0 < INNER; k0 += 16) {
        const int cur = (k0 >> 4) & 1;
        const int nxt = cur ^ 1;
        if (k0 + 16 < INNER) {
            #pragma unroll
            for (int i = 0; i < 8; i++) {
                int kk = lk0 + 2 * i;
                cp4(&As[nxt][kk][lm], &g_att[(size_t)(m0 + lm) * INNER + k0 + 16 + kk]);
                cp4(&Bs[nxt][kk][lm], &wout[(k0 + 16 + kk) * DIM + n0 + lm]);
            }
            CP_COMMIT();
            CP_WAIT(1);
        } else {
            CP_WAIT(0);
        }
        __syncthreads();
        #pragma unroll
        for (int k = 0; k < 16; k++) {
            float a[8], b[8];
            *(float4*)(a)     = *(const float4*)&As[cur][k][tr];
            *(float4*)(a + 4) = *(const float4*)&As[cur][k][tr + 4];
            *(float4*)(b)     = *(const float4*)&Bs[cur][k][tc];
            *(float4*)(b + 4) = *(const float4*)&Bs[cur][k][tc + 4];
            #pragma unroll
            for (int i = 0; i < 8; i++)
                #pragma unroll
                for (int j = 0; j < 8; j++)
                    acc[i][j] += a[i] * b[j];
        }
        __syncthreads();
    }

    #pragma unroll
    for (int i = 0; i < 8; i++) {
        int ro = rowoff[tr + i];
        #pragma unroll
        for (int j = 0; j < 8; j++) {
            int c = n0 + tc + j;
            out[ro + c * SP] = acc[i][j] + bout[c];
        }
    }
}

// ---------------------------------------------------------------------------
extern "C" void kernel_launch(void* const* d_in, const int* in_sizes, int n_in,
                              void* d_out, int out_size) {
    const float* x    = (const float*)d_in[0];
    const float* pos  = (const float*)d_in[1];
    const float* wqkv = (const float*)d_in[2];
    const float* wout = (const float*)d_in[3];
    const float* bout = (const float*)d_in[4];

    float* out      = (float*)d_out;
    float* attn_out = out + (size_t)BATCH * DIM * SP;

    dim3 g1(M_TOTAL / 128, QKV_N / 128);
    qkv_gemm<<<g1, 256>>>(x, wqkv);

    attn_kernel<<<BATCH * NWIN * HEADS, 256>>>(pos, attn_out);

    dim3 g3(M_TOTAL / 128, DIM / 128);
    out_gemm<<<g3, 256>>>(wout, bout, out);
}

// round 6
// speedup vs baseline: 1.0073x; 1.0073x over previous
#include <cuda_runtime.h>
#include <cstdint>

#define BATCH 32
#define DIM   256
#define HW    56
#define SP    (HW*HW)        // 3136
#define PW    7
#define PP    49
#define DD    3
#define N1    8
#define N2    8
#define NWIN  64
#define HEADS 8
#define DH    32
#define INNER 256
#define QKV_N 768
#define M_TOTAL (BATCH*NWIN*PP)   // 100352

__device__ float g_qkv[(size_t)M_TOTAL * QKV_N];   // ~308 MB
__device__ float g_att[(size_t)M_TOTAL * INNER];   // ~103 MB

typedef unsigned long long u64;

__device__ __forceinline__ u64 pack_dup(float x) {
    u64 r; unsigned u = __float_as_uint(x);
    asm("mov.b64 %0, {%1, %1};" : "=l"(r) : "r"(u));
    return r;
}
__device__ __forceinline__ void fma2(u64& d, u64 a, u64 b) {
    asm("fma.rn.f32x2 %0, %1, %2, %0;" : "+l"(d) : "l"(a), "l"(b));
}
__device__ __forceinline__ void mul2(u64& d, u64 a, u64 b) {
    asm("mul.rn.f32x2 %0, %1, %2;" : "=l"(d) : "l"(a), "l"(b));
}
__device__ __forceinline__ float2 unpack2(u64 v) {
    unsigned lo, hi;
    asm("mov.b64 {%0, %1}, %2;" : "=r"(lo), "=r"(hi) : "l"(v));
    return make_float2(__uint_as_float(lo), __uint_as_float(hi));
}

__device__ __forceinline__ int row_to_off(int r) {
    int bi  = r / (NWIN * PP);
    int rem = r % (NWIN * PP);
    int w   = rem / PP;
    int t   = rem % PP;
    int n1i = w / N2, n2i = w % N2;
    int py  = t / PW, px  = t % PW;
    int hh  = (n1i * PW + py + DD) % HW;
    int ww  = (n2i * PW + px + DD) % HW;
    return bi * DIM * SP + hh * HW + ww;
}

// ---------------------------------------------------------------------------
// Kernel 1: qkv = window(roll(x)) @ w_qkv — 128x128 tile, 8x8 micro, f32x2 FMA
// ---------------------------------------------------------------------------
__global__ void __launch_bounds__(256) qkv_gemm(const float* __restrict__ x,
                                                const float* __restrict__ wqkv) {
    __shared__ float As[16][128];
    __shared__ float Bs[16][128];
    __shared__ int   rowoff[128];

    const int m0  = blockIdx.x * 128;
    const int n0  = blockIdx.y * 128;
    const int tid = threadIdx.x;

    if (tid < 128) rowoff[tid] = row_to_off(m0 + tid);
    __syncthreads();

    const int lm  = tid & 127;
    const int lk0 = tid >> 7;      // 0..1
    const int tr  = (tid >> 4) * 8;
    const int tc  = (tid & 15) * 8;

    u64 acc2[8][4] = {};

    for (int k0 = 0; k0 < DIM; k0 += 16) {
        #pragma unroll
        for (int i = 0; i < 8; i++) {
            int kk = lk0 + 2 * i;
            As[kk][lm] = x[rowoff[lm] + (k0 + kk) * SP];
            Bs[kk][lm] = wqkv[(k0 + kk) * QKV_N + n0 + lm];
        }
        __syncthreads();
        #pragma unroll
        for (int k = 0; k < 16; k++) {
            float a[8];
            *(float4*)(a)     = *(const float4*)&As[k][tr];
            *(float4*)(a + 4) = *(const float4*)&As[k][tr + 4];
            u64 b2[4];
            *(ulonglong2*)(b2)     = *(const ulonglong2*)&Bs[k][tc];
            *(ulonglong2*)(b2 + 2) = *(const ulonglong2*)&Bs[k][tc + 4];
            #pragma unroll
            for (int i = 0; i < 8; i++) {
                u64 a2 = pack_dup(a[i]);
                #pragma unroll
                for (int jp = 0; jp < 4; jp++)
                    fma2(acc2[i][jp], a2, b2[jp]);
            }
        }
        __syncthreads();
    }

    #pragma unroll
    for (int i = 0; i < 8; i++) {
        u64* dst = (u64*)&g_qkv[(size_t)(m0 + tr + i) * QKV_N + n0 + tc];
        ulonglong2 s0, s1;
        s0.x = acc2[i][0]; s0.y = acc2[i][1];
        s1.x = acc2[i][2]; s1.y = acc2[i][3];
        *(ulonglong2*)(dst)     = s0;
        *(ulonglong2*)(dst + 2) = s1;
    }
}

// ---------------------------------------------------------------------------
// Kernel 2: per (b, window, head) attention. Parallel softmax, f32x2 math.
// ---------------------------------------------------------------------------
__global__ void __launch_bounds__(256) attn_kernel(const float* __restrict__ pos,
                                                   float* __restrict__ attn_out) {
    const int bid  = blockIdx.x;                // bi*NWIN*HEADS + w*HEADS + head
    const int head = bid % HEADS;
    const int bw   = bid / HEADS;
    const int w    = bw % NWIN;
    const int bi   = bw / NWIN;
    const int tid  = threadIdx.x;

    __shared__ float q[PP][DH];
    __shared__ float kT[DH][52];      // transposed K (row stride 208B, 16B aligned)
    __shared__ float v[PP][DH];
    __shared__ float dots[PP][53];
    __shared__ float poss[169];
    __shared__ float cpart[PP][13];
    __shared__ float rowm[PP], rowinv[PP];

    const float* base = g_qkv + (size_t)(bi * NWIN + w) * PP * QKV_N + head * DH;
    for (int idx = tid; idx < PP * 8; idx += 256) {
        int t = idx >> 3, c = idx & 7;
        const float* rowp = base + (size_t)t * QKV_N + c * 4;
        float4 qf = *(const float4*)(rowp);
        float4 kf = *(const float4*)(rowp + INNER);
        float4 vf = *(const float4*)(rowp + 2 * INNER);
        *(float4*)&q[t][c * 4] = qf;
        *(float4*)&v[t][c * 4] = vf;
        int d = c * 4;
        kT[d][t] = kf.x; kT[d + 1][t] = kf.y; kT[d + 2][t] = kf.z; kT[d + 3][t] = kf.w;
    }
    if (tid < DH) { kT[tid][49] = 0.f; kT[tid][50] = 0.f; kT[tid][51] = 0.f; }
    for (int idx = tid; idx < 169; idx += 256) poss[idx] = pos[idx];
    __syncthreads();

    const bool m_ul = (w >= NWIN - N2);                                          // 56..63
    const bool m_lr = (w >= NWIN - N1 - 1) && ((w - (NWIN - N1 - 1)) % N1 == 0); // {55,63}
    const float NEG = -1e30f;
    const float scale = 0.17677669529663687f;  // 1/sqrt(32)

    // Pass 1: dots (f32x2 over j) + per-chunk max
    for (int idx = tid; idx < PP * 13; idx += 256) {
        int i = idx / 13, jc = idx % 13, j0 = jc * 4;
        u64 s2[2] = {};
        #pragma unroll
        for (int d = 0; d < DH; d++) {
            u64 q2 = pack_dup(q[i][d]);
            ulonglong2 k2 = *(const ulonglong2*)&kT[d][j0];
            fma2(s2[0], q2, k2.x);
            fma2(s2[1], q2, k2.y);
        }
        float2 p0 = unpack2(s2[0]), p1 = unpack2(s2[1]);
        float sv[4] = {p0.x, p0.y, p1.x, p1.y};
        int iy = i / PW, ix = i % PW;
        float cm = -3.4e38f;
        #pragma unroll
        for (int jj = 0; jj < 4; jj++) {
            int j = j0 + jj;
            if (j < PP) {
                int jy = j / PW, jx = j % PW;
                float val = sv[jj] * scale + poss[(jy - iy + 6) * 13 + (jx - ix + 6)];
                if (m_ul && ((iy >= 4) != (jy >= 4))) val = NEG;
                if (m_lr && ((ix >= 4) != (jx >= 4))) val = NEG;
                dots[i][j] = val;
                cm = fmaxf(cm, val);
            }
        }
        cpart[i][jc] = cm;
    }
    __syncthreads();

    if (tid < PP) {
        float m = cpart[tid][0];
        #pragma unroll
        for (int c = 1; c < 13; c++) m = fmaxf(m, cpart[tid][c]);
        rowm[tid] = m;
    }
    __syncthreads();

    // Pass 2: exp + per-chunk sum
    for (int idx = tid; idx < PP * 13; idx += 256) {
        int i = idx / 13, jc = idx % 13, j0 = jc * 4;
        float m = rowm[i];
        float ps = 0.f;
        #pragma unroll
        for (int jj = 0; jj < 4; jj++) {
            int j = j0 + jj;
            if (j < PP) {
                float e = __expf(dots[i][j] - m);
                dots[i][j] = e;
                ps += e;
            }
        }
        cpart[i][jc] = ps;
    }
    __syncthreads();

    if (tid < PP) {
        float s = 0.f;
        #pragma unroll
        for (int c = 0; c < 13; c++) s += cpart[tid][c];
        rowinv[tid] = 1.0f / s;
    }
    __syncthreads();

    // attn output (normalized on the fly)
    float* ao = attn_out + (size_t)bid * (PP * PP);
    for (int idx = tid; idx < PP * PP; idx += 256) {
        int i = idx / PP, j = idx % PP;
        ao[idx] = dots[i][j] * rowinv[i];
    }

    // attn @ v — float4 over d per thread, f32x2 FMA
    float* ob = g_att + (size_t)(bi * NWIN + w) * PP * INNER + head * DH;
    for (int idx = tid; idx < PP * 8; idx += 256) {
        int i = idx >> 3, d0 = (idx & 7) * 4;
        u64 s2[2] = {};
        #pragma unroll
        for (int j = 0; j < PP; j++) {
            u64 p2 = pack_dup(dots[i][j]);
            ulonglong2 v2 = *(const ulonglong2*)&v[j][d0];
            fma2(s2[0], p2, v2.x);
            fma2(s2[1], p2, v2.y);
        }
        u64 r2 = pack_dup(rowinv[i]);
        ulonglong2 o2;
        mul2(o2.x, s2[0], r2);
        mul2(o2.y, s2[1], r2);
        *(ulonglong2*)&ob[(size_t)i * INNER + d0] = o2;
    }
}

// ---------------------------------------------------------------------------
// Kernel 3: out = g_att @ w_out + b_out, smem-staged coalesced scatter
// ---------------------------------------------------------------------------
__global__ void __launch_bounds__(256) out_gemm(const float* __restrict__ wout,
                                                const float* __restrict__ bout,
                                                float* __restrict__ out) {
    __shared__ union {
        struct { float As[16][128]; float Bs[16][128]; } mm;
        float sbuf[128][129];
    } sh;
    __shared__ int   rowoff[128];
    __shared__ float bout_s[128];

    const int m0  = blockIdx.x * 128;
    const int n0  = blockIdx.y * 128;
    const int tid = threadIdx.x;

    if (tid < 128) {
        rowoff[tid] = row_to_off(m0 + tid);
        bout_s[tid] = bout[n0 + tid];
    }
    __syncthreads();

    const int lm  = tid & 127;
    const int lk0 = tid >> 7;
    const int tr  = (tid >> 4) * 8;
    const int tc  = (tid & 15) * 8;

    u64 acc2[8][4] = {};

    for (int k0 = 0; k0 < INNER; k0 += 16) {
        #pragma unroll
        for (int i = 0; i < 8; i++) {
            int kk = lk0 + 2 * i;
            sh.mm.As[kk][lm] = g_att[(size_t)(m0 + lm) * INNER + k0 + kk];
            sh.mm.Bs[kk][lm] = wout[(k0 + kk) * DIM + n0 + lm];
        }
        __syncthreads();
        #pragma unroll
        for (int k = 0; k < 16; k++) {
            float a[8];
            *(float4*)(a)     = *(const float4*)&sh.mm.As[k][tr];
            *(float4*)(a + 4) = *(const float4*)&sh.mm.As[k][tr + 4];
            u64 b2[4];
            *(ulonglong2*)(b2)     = *(const ulonglong2*)&sh.mm.Bs[k][tc];
            *(ulonglong2*)(b2 + 2) = *(const ulonglong2*)&sh.mm.Bs[k][tc + 4];
            #pragma unroll
            for (int i = 0; i < 8; i++) {
                u64 a2 = pack_dup(a[i]);
                #pragma unroll
                for (int jp = 0; jp < 4; jp++)
                    fma2(acc2[i][jp], a2, b2[jp]);
            }
        }
        __syncthreads();
    }

    // stage tile into smem (row stride 129 -> conflict-free column reads)
    #pragma unroll
    for (int i = 0; i < 8; i++) {
        #pragma unroll
        for (int jp = 0; jp < 4; jp++) {
            float2 p = unpack2(acc2[i][jp]);
            sh.sbuf[tr + i][tc + 2 * jp]     = p.x;
            sh.sbuf[tr + i][tc + 2 * jp + 1] = p.y;
        }
    }
    __syncthreads();

    // coalesced-ish scatter: consecutive threads sweep m (7-contiguous in w)
    #pragma unroll
    for (int it = 0; it < 64; it++) {
        int flat = it * 256 + tid;
        int m = flat & 127;
        int c = flat >> 7;
        out[rowoff[m] + (n0 + c) * SP] = sh.sbuf[m][c] + bout_s[c];
    }
}

// ---------------------------------------------------------------------------
extern "C" void kernel_launch(void* const* d_in, const int* in_sizes, int n_in,
                              void* d_out, int out_size) {
    const float* x    = (const float*)d_in[0];
    const float* pos  = (const float*)d_in[1];
    const float* wqkv = (const float*)d_in[2];
    const float* wout = (const float*)d_in[3];
    const float* bout = (const float*)d_in[4];

    float* out      = (float*)d_out;
    float* attn_out = out + (size_t)BATCH * DIM * SP;

    dim3 g1(M_TOTAL / 128, QKV_N / 128);
    qkv_gemm<<<g1, 256>>>(x, wqkv);

    attn_kernel<<<BATCH * NWIN * HEADS, 256>>>(pos, attn_out);

    dim3 g3(M_TOTAL / 128, DIM / 128);
    out_gemm<<<g3, 256>>>(wout, bout, out);
}

// round 7
// speedup vs baseline: 1.4464x; 1.4360x over previous
#include <cuda_runtime.h>
#include <cstdint>

#define BATCH 32
#define DIM   256
#define HW    56
#define SP    (HW*HW)        // 3136
#define PW    7
#define PP    49
#define DD    3
#define N1    8
#define N2    8
#define NWIN  64
#define HEADS 8
#define DH    32
#define INNER 256
#define QKV_N 768
#define M_TOTAL (BATCH*NWIN*PP)   // 100352

__device__ float g_qkv[(size_t)M_TOTAL * QKV_N];   // ~308 MB
__device__ float g_att[(size_t)M_TOTAL * INNER];   // ~103 MB

typedef unsigned long long u64;

__device__ __forceinline__ u64 pack_dup(float x) {
    u64 r; unsigned u = __float_as_uint(x);
    asm("mov.b64 %0, {%1, %1};" : "=l"(r) : "r"(u));
    return r;
}
__device__ __forceinline__ void fma2(u64& d, u64 a, u64 b) {
    asm("fma.rn.f32x2 %0, %1, %2, %0;" : "+l"(d) : "l"(a), "l"(b));
}
__device__ __forceinline__ void mul2(u64& d, u64 a, u64 b) {
    asm("mul.rn.f32x2 %0, %1, %2;" : "=l"(d) : "l"(a), "l"(b));
}
__device__ __forceinline__ float2 unpack2(u64 v) {
    unsigned lo, hi;
    asm("mov.b64 {%0, %1}, %2;" : "=r"(lo), "=r"(hi) : "l"(v));
    return make_float2(__uint_as_float(lo), __uint_as_float(hi));
}

__device__ __forceinline__ int row_to_off(int r) {
    int bi  = r / (NWIN * PP);
    int rem = r % (NWIN * PP);
    int w   = rem / PP;
    int t   = rem % PP;
    int n1i = w / N2, n2i = w % N2;
    int py  = t / PW, px  = t % PW;
    int hh  = (n1i * PW + py + DD) % HW;
    int ww  = (n2i * PW + px + DD) % HW;
    return bi * DIM * SP + hh * HW + ww;
}

// conflict-free lane mapping: warp tile 32x64, lane (r,c) = (lane&3, lane>>2)
#define TR_OF(tid) ((((tid) >> 5) & 3) * 32 + ((tid) & 3) * 8)
#define TC_OF(tid) ((((tid) >> 7)) * 64 + ((((tid) & 31) >> 2)) * 8)

// ---------------------------------------------------------------------------
// Kernel 1: qkv = window(roll(x)) @ w_qkv — 128x128 tile, 8x8 micro, f32x2
// ---------------------------------------------------------------------------
__global__ void __launch_bounds__(256) qkv_gemm(const float* __restrict__ x,
                                                const float* __restrict__ wqkv) {
    __shared__ float As[16][128];
    __shared__ float Bs[16][128];
    __shared__ int   rowoff[128];

    const int m0  = blockIdx.x * 128;
    const int n0  = blockIdx.y * 128;
    const int tid = threadIdx.x;

    if (tid < 128) rowoff[tid] = row_to_off(m0 + tid);
    __syncthreads();

    const int lm  = tid & 127;
    const int lk0 = tid >> 7;      // 0..1
    const int tr  = TR_OF(tid);
    const int tc  = TC_OF(tid);

    u64 acc2[8][4] = {};

    for (int k0 = 0; k0 < DIM; k0 += 16) {
        #pragma unroll
        for (int i = 0; i < 8; i++) {
            int kk = lk0 + 2 * i;
            As[kk][lm] = x[rowoff[lm] + (k0 + kk) * SP];
            Bs[kk][lm] = wqkv[(k0 + kk) * QKV_N + n0 + lm];
        }
        __syncthreads();
        #pragma unroll
        for (int k = 0; k < 16; k++) {
            float a[8];
            *(float4*)(a)     = *(const float4*)&As[k][tr];
            *(float4*)(a + 4) = *(const float4*)&As[k][tr + 4];
            u64 b2[4];
            *(ulonglong2*)(b2)     = *(const ulonglong2*)&Bs[k][tc];
            *(ulonglong2*)(b2 + 2) = *(const ulonglong2*)&Bs[k][tc + 4];
            #pragma unroll
            for (int i = 0; i < 8; i++) {
                u64 a2 = pack_dup(a[i]);
                #pragma unroll
                for (int jp = 0; jp < 4; jp++)
                    fma2(acc2[i][jp], a2, b2[jp]);
            }
        }
        __syncthreads();
    }

    #pragma unroll
    for (int i = 0; i < 8; i++) {
        u64* dst = (u64*)&g_qkv[(size_t)(m0 + tr + i) * QKV_N + n0 + tc];
        ulonglong2 s0, s1;
        s0.x = acc2[i][0]; s0.y = acc2[i][1];
        s1.x = acc2[i][2]; s1.y = acc2[i][3];
        *(ulonglong2*)(dst)     = s0;
        *(ulonglong2*)(dst + 2) = s1;
    }
}

// ---------------------------------------------------------------------------
// Kernel 2: per (b, window, head) attention. 4x4 micro-tiled QK & AV.
// ---------------------------------------------------------------------------
__global__ void __launch_bounds__(256) attn_kernel(const float* __restrict__ pos,
                                                   float* __restrict__ attn_out) {
    const int bid  = blockIdx.x;                // bi*NWIN*HEADS + w*HEADS + head
    const int head = bid % HEADS;
    const int bw   = bid / HEADS;
    const int w    = bw % NWIN;
    const int bi   = bw / NWIN;
    const int tid  = threadIdx.x;

    __shared__ float qT[DH][52];      // transposed Q (16B-aligned rows)
    __shared__ float kT[DH][52];      // transposed K
    __shared__ float v[PP][DH];
    __shared__ float dots[PP][56];    // stride 56: 16B-aligned float4 rows
    __shared__ float poss[169];
    __shared__ float cpart[PP][13];
    __shared__ float rowm[PP], rowinv[PP];

    const float* base = g_qkv + (size_t)(bi * NWIN + w) * PP * QKV_N + head * DH;
    for (int idx = tid; idx < PP * 8; idx += 256) {
        int t = idx >> 3, c = idx & 7;
        const float* rowp = base + (size_t)t * QKV_N + c * 4;
        float4 qf = *(const float4*)(rowp);
        float4 kf = *(const float4*)(rowp + INNER);
        float4 vf = *(const float4*)(rowp + 2 * INNER);
        *(float4*)&v[t][c * 4] = vf;
        int d = c * 4;
        qT[d][t] = qf.x; qT[d + 1][t] = qf.y; qT[d + 2][t] = qf.z; qT[d + 3][t] = qf.w;
        kT[d][t] = kf.x; kT[d + 1][t] = kf.y; kT[d + 2][t] = kf.z; kT[d + 3][t] = kf.w;
    }
    if (tid < DH) {
        qT[tid][49] = 0.f; qT[tid][50] = 0.f; qT[tid][51] = 0.f;
        kT[tid][49] = 0.f; kT[tid][50] = 0.f; kT[tid][51] = 0.f;
    }
    for (int idx = tid; idx < 169; idx += 256) poss[idx] = pos[idx];
    __syncthreads();

    const bool m_ul = (w >= NWIN - N2);                                          // 56..63
    const bool m_lr = (w >= NWIN - N1 - 1) && ((w - (NWIN - N1 - 1)) % N1 == 0); // {55,63}
    const float NEG = -1e30f;
    const float scale = 0.17677669529663687f;  // 1/sqrt(32)

    // Pass 1: dots 4x4 micro-tile per thread (13 i-chunks x 13 j-chunks = 169)
    if (tid < 169) {
        int ic = tid / 13, jc = tid % 13;
        int i0 = ic * 4, j0 = jc * 4;
        u64 acc2[4][2] = {};
        #pragma unroll
        for (int d = 0; d < DH; d++) {
            float4 qf = *(const float4*)&qT[d][i0];
            ulonglong2 k2 = *(const ulonglong2*)&kT[d][j0];
            float qa[4] = {qf.x, qf.y, qf.z, qf.w};
            #pragma unroll
            for (int ii = 0; ii < 4; ii++) {
                u64 q2 = pack_dup(qa[ii]);
                fma2(acc2[ii][0], q2, k2.x);
                fma2(acc2[ii][1], q2, k2.y);
            }
        }
        #pragma unroll
        for (int ii = 0; ii < 4; ii++) {
            int i = i0 + ii;
            if (i < PP) {
                float2 p0 = unpack2(acc2[ii][0]), p1 = unpack2(acc2[ii][1]);
                float sv[4] = {p0.x, p0.y, p1.x, p1.y};
                int iy = i / PW, ix = i % PW;
                float outv[4];
                float cm = -3.4e38f;
                #pragma unroll
                for (int jj = 0; jj < 4; jj++) {
                    int j = j0 + jj;
                    float val = NEG;
                    if (j < PP) {
                        int jy = j / PW, jx = j % PW;
                        val = sv[jj] * scale + poss[(jy - iy + 6) * 13 + (jx - ix + 6)];
                        if (m_ul && ((iy >= 4) != (jy >= 4))) val = NEG;
                        if (m_lr && ((ix >= 4) != (jx >= 4))) val = NEG;
                        cm = fmaxf(cm, val);
                    }
                    outv[jj] = val;
                }
                *(float4*)&dots[i][j0] = make_float4(outv[0], outv[1], outv[2], outv[3]);
                cpart[i][jc] = cm;
            }
        }
    }
    __syncthreads();

    if (tid < PP) {
        float m = cpart[tid][0];
        #pragma unroll
        for (int c = 1; c < 13; c++) m = fmaxf(m, cpart[tid][c]);
        rowm[tid] = m;
    }
    __syncthreads();

    // Pass 2: exp + per-chunk sum (637 items)
    for (int idx = tid; idx < PP * 13; idx += 256) {
        int i = idx / 13, jc = idx % 13, j0 = jc * 4;
        float m = rowm[i];
        float4 dv = *(const float4*)&dots[i][j0];
        float xv[4] = {dv.x, dv.y, dv.z, dv.w};
        float ev[4];
        float ps = 0.f;
        #pragma unroll
        for (int jj = 0; jj < 4; jj++) {
            float e = (j0 + jj < PP) ? __expf(xv[jj] - m) : 0.f;
            ev[jj] = e;
            ps += e;
        }
        *(float4*)&dots[i][j0] = make_float4(ev[0], ev[1], ev[2], ev[3]);
        cpart[i][jc] = ps;
    }
    __syncthreads();

    if (tid < PP) {
        float s = 0.f;
        #pragma unroll
        for (int c = 0; c < 13; c++) s += cpart[tid][c];
        rowinv[tid] = 1.0f / s;
    }
    __syncthreads();

    // attn output (normalized)
    float* ao = attn_out + (size_t)bid * (PP * PP);
    for (int idx = tid; idx < PP * PP; idx += 256) {
        int i = idx / PP, j = idx % PP;
        ao[idx] = dots[i][j] * rowinv[i];
    }

    // attn @ v — 4x4 micro-tile over (i, d): 13 i-chunks x 8 d-chunks = 104
    float* ob = g_att + (size_t)(bi * NWIN + w) * PP * INNER + head * DH;
    if (tid < 104) {
        int ic = tid / 8, dc = tid % 8;
        int i0 = ic * 4, d0 = dc * 4;
        u64 acc2[4][2] = {};
        #pragma unroll
        for (int j = 0; j < PP; j++) {
            ulonglong2 v2 = *(const ulonglong2*)&v[j][d0];
            #pragma unroll
            for (int ii = 0; ii < 4; ii++) {
                u64 p2 = pack_dup(dots[i0 + ii][j]);
                fma2(acc2[ii][0], p2, v2.x);
                fma2(acc2[ii][1], p2, v2.y);
            }
        }
        #pragma unroll
        for (int ii = 0; ii < 4; ii++) {
            int i = i0 + ii;
            if (i < PP) {
                u64 r2 = pack_dup(rowinv[i]);
                ulonglong2 o2;
                mul2(o2.x, acc2[ii][0], r2);
                mul2(o2.y, acc2[ii][1], r2);
                *(ulonglong2*)&ob[(size_t)i * INNER + d0] = o2;
            }
        }
    }
}

// ---------------------------------------------------------------------------
// Kernel 3: out = g_att @ w_out + b_out, smem-staged coalesced scatter
// ---------------------------------------------------------------------------
__global__ void __launch_bounds__(256) out_gemm(const float* __restrict__ wout,
                                                const float* __restrict__ bout,
                                                float* __restrict__ out) {
    __shared__ union U {
        struct { float As[16][128]; float Bs[16][128]; } mm;
        float sbuf[128][129];
        __device__ U() {}
    } sh;
    __shared__ int   rowoff[128];
    __shared__ float bout_s[128];

    const int m0  = blockIdx.x * 128;
    const int n0  = blockIdx.y * 128;
    const int tid = threadIdx.x;

    if (tid < 128) {
        rowoff[tid] = row_to_off(m0 + tid);
        bout_s[tid] = bout[n0 + tid];
    }
    __syncthreads();

    const int lm  = tid & 127;
    const int lk0 = tid >> 7;
    const int tr  = TR_OF(tid);
    const int tc  = TC_OF(tid);

    u64 acc2[8][4] = {};

    for (int k0 = 0; k0 < INNER; k0 += 16) {
        #pragma unroll
        for (int i = 0; i < 8; i++) {
            int kk = lk0 + 2 * i;
            sh.mm.As[kk][lm] = g_att[(size_t)(m0 + lm) * INNER + k0 + kk];
            sh.mm.Bs[kk][lm] = wout[(k0 + kk) * DIM + n0 + lm];
        }
        __syncthreads();
        #pragma unroll
        for (int k = 0; k < 16; k++) {
            float a[8];
            *(float4*)(a)     = *(const float4*)&sh.mm.As[k][tr];
            *(float4*)(a + 4) = *(const float4*)&sh.mm.As[k][tr + 4];
            u64 b2[4];
            *(ulonglong2*)(b2)     = *(const ulonglong2*)&sh.mm.Bs[k][tc];
            *(ulonglong2*)(b2 + 2) = *(const ulonglong2*)&sh.mm.Bs[k][tc + 4];
            #pragma unroll
            for (int i = 0; i < 8; i++) {
                u64 a2 = pack_dup(a[i]);
                #pragma unroll
                for (int jp = 0; jp < 4; jp++)
                    fma2(acc2[i][jp], a2, b2[jp]);
            }
        }
        __syncthreads();
    }

    // stage tile into smem (row stride 129 -> conflict-free column reads)
    #pragma unroll
    for (int i = 0; i < 8; i++) {
        #pragma unroll
        for (int jp = 0; jp < 4; jp++) {
            float2 p = unpack2(acc2[i][jp]);
            sh.sbuf[tr + i][tc + 2 * jp]     = p.x;
            sh.sbuf[tr + i][tc + 2 * jp + 1] = p.y;
        }
    }
    __syncthreads();

    // scatter: consecutive threads sweep m (7-contiguous runs in w)
    #pragma unroll
    for (int it = 0; it < 64; it++) {
        int flat = it * 256 + tid;
        int m = flat & 127;
        int c = flat >> 7;
        out[rowoff[m] + (n0 + c) * SP] = sh.sbuf[m][c] + bout_s[c];
    }
}

// ---------------------------------------------------------------------------
extern "C" void kernel_launch(void* const* d_in, const int* in_sizes, int n_in,
                              void* d_out, int out_size) {
    const float* x    = (const float*)d_in[0];
    const float* pos  = (const float*)d_in[1];
    const float* wqkv = (const float*)d_in[2];
    const float* wout = (const float*)d_in[3];
    const float* bout = (const float*)d_in[4];

    float* out      = (float*)d_out;
    float* attn_out = out + (size_t)BATCH * DIM * SP;

    dim3 g1(M_TOTAL / 128, QKV_N / 128);
    qkv_gemm<<<g1, 256>>>(x, wqkv);

    attn_kernel<<<BATCH * NWIN * HEADS, 256>>>(pos, attn_out);

    dim3 g3(M_TOTAL / 128, DIM / 128);
    out_gemm<<<g3, 256>>>(wout, bout, out);
}

// round 8
// speedup vs baseline: 1.4939x; 1.0328x over previous
#include <cuda_runtime.h>
#include <cstdint>

#define BATCH 32
#define DIM   256
#define HW    56
#define SP    (HW*HW)        // 3136
#define PW    7
#define PP    49
#define DD    3
#define N1    8
#define N2    8
#define NWIN  64
#define HEADS 8
#define DH    32
#define INNER 256
#define QKV_N 768
#define M_TOTAL (BATCH*NWIN*PP)   // 100352

__device__ float g_qkv[(size_t)M_TOTAL * QKV_N];   // ~308 MB
__device__ float g_att[(size_t)M_TOTAL * INNER];   // ~103 MB

typedef unsigned long long u64;

__device__ __forceinline__ u64 pack_dup(float x) {
    u64 r; unsigned u = __float_as_uint(x);
    asm("mov.b64 %0, {%1, %1};" : "=l"(r) : "r"(u));
    return r;
}
__device__ __forceinline__ void fma2(u64& d, u64 a, u64 b) {
    asm("fma.rn.f32x2 %0, %1, %2, %0;" : "+l"(d) : "l"(a), "l"(b));
}
__device__ __forceinline__ void mul2(u64& d, u64 a, u64 b) {
    asm("mul.rn.f32x2 %0, %1, %2;" : "=l"(d) : "l"(a), "l"(b));
}
__device__ __forceinline__ float2 unpack2(u64 v) {
    unsigned lo, hi;
    asm("mov.b64 {%0, %1}, %2;" : "=r"(lo), "=r"(hi) : "l"(v));
    return make_float2(__uint_as_float(lo), __uint_as_float(hi));
}

__device__ __forceinline__ int row_to_off(int r) {
    int bi  = r / (NWIN * PP);
    int rem = r % (NWIN * PP);
    int w   = rem / PP;
    int t   = rem % PP;
    int n1i = w / N2, n2i = w % N2;
    int py  = t / PW, px  = t % PW;
    int hh  = (n1i * PW + py + DD) % HW;
    int ww  = (n2i * PW + px + DD) % HW;
    return bi * DIM * SP + hh * HW + ww;
}

// conflict-free lane mapping: warp tile 32x64, lane (r,c) = (lane&3, lane>>2)
#define TR_OF(tid) ((((tid) >> 5) & 3) * 32 + ((tid) & 3) * 8)
#define TC_OF(tid) ((((tid) >> 7)) * 64 + ((((tid) & 31) >> 2)) * 8)

// ---------------------------------------------------------------------------
// Kernel 1: qkv = window(roll(x)) @ w_qkv — 128x128 tile, 8x8 micro, f32x2
// grid = (n-tiles, m-tiles): n-tiles of one m-tile adjacent -> x L2 reuse
// ---------------------------------------------------------------------------
__global__ void __launch_bounds__(256) qkv_gemm(const float* __restrict__ x,
                                                const float* __restrict__ wqkv) {
    __shared__ float As[16][128];
    __shared__ float Bs[16][128];
    __shared__ int   rowoff[128];

    const int m0  = blockIdx.y * 128;
    const int n0  = blockIdx.x * 128;
    const int tid = threadIdx.x;

    if (tid < 128) rowoff[tid] = row_to_off(m0 + tid);
    __syncthreads();

    const int lm  = tid & 127;
    const int lk0 = tid >> 7;      // 0..1
    const int tr  = TR_OF(tid);
    const int tc  = TC_OF(tid);

    u64 acc2[8][4] = {};

    for (int k0 = 0; k0 < DIM; k0 += 16) {
        #pragma unroll
        for (int i = 0; i < 8; i++) {
            int kk = lk0 + 2 * i;
            As[kk][lm] = x[rowoff[lm] + (k0 + kk) * SP];
            Bs[kk][lm] = wqkv[(k0 + kk) * QKV_N + n0 + lm];
        }
        __syncthreads();
        #pragma unroll
        for (int k = 0; k < 16; k++) {
            float a[8];
            *(float4*)(a)     = *(const float4*)&As[k][tr];
            *(float4*)(a + 4) = *(const float4*)&As[k][tr + 4];
            u64 b2[4];
            *(ulonglong2*)(b2)     = *(const ulonglong2*)&Bs[k][tc];
            *(ulonglong2*)(b2 + 2) = *(const ulonglong2*)&Bs[k][tc + 4];
            #pragma unroll
            for (int i = 0; i < 8; i++) {
                u64 a2 = pack_dup(a[i]);
                #pragma unroll
                for (int jp = 0; jp < 4; jp++)
                    fma2(acc2[i][jp], a2, b2[jp]);
            }
        }
        __syncthreads();
    }

    #pragma unroll
    for (int i = 0; i < 8; i++) {
        u64* dst = (u64*)&g_qkv[(size_t)(m0 + tr + i) * QKV_N + n0 + tc];
        ulonglong2 s0, s1;
        s0.x = acc2[i][0]; s0.y = acc2[i][1];
        s1.x = acc2[i][2]; s1.y = acc2[i][3];
        *(ulonglong2*)(dst)     = s0;
        *(ulonglong2*)(dst + 2) = s1;
    }
}

// ---------------------------------------------------------------------------
// Kernel 2: per (b, window, head) attention. 4x4 micro-tiled QK & AV,
// attn-write overlapped with AV via thread split.
// ---------------------------------------------------------------------------
__global__ void __launch_bounds__(256) attn_kernel(const float* __restrict__ pos,
                                                   float* __restrict__ attn_out) {
    const int bid  = blockIdx.x;                // bi*NWIN*HEADS + w*HEADS + head
    const int head = bid % HEADS;
    const int bw   = bid / HEADS;
    const int w    = bw % NWIN;
    const int bi   = bw / NWIN;
    const int tid  = threadIdx.x;

    __shared__ float qT[DH][52];      // transposed Q (16B-aligned rows)
    __shared__ float kT[DH][52];      // transposed K
    __shared__ float v[PP][DH];
    __shared__ float dots[PP][56];    // stride 56: 16B-aligned float4 rows
    __shared__ float poss[169];
    __shared__ float cpart[PP][13];
    __shared__ float rowm[PP], rowinv[PP];

    const float* base = g_qkv + (size_t)(bi * NWIN + w) * PP * QKV_N + head * DH;
    for (int idx = tid; idx < PP * 8; idx += 256) {
        int t = idx >> 3, c = idx & 7;
        const float* rowp = base + (size_t)t * QKV_N + c * 4;
        float4 qf = *(const float4*)(rowp);
        float4 kf = *(const float4*)(rowp + INNER);
        float4 vf = *(const float4*)(rowp + 2 * INNER);
        *(float4*)&v[t][c * 4] = vf;
        int d = c * 4;
        qT[d][t] = qf.x; qT[d + 1][t] = qf.y; qT[d + 2][t] = qf.z; qT[d + 3][t] = qf.w;
        kT[d][t] = kf.x; kT[d + 1][t] = kf.y; kT[d + 2][t] = kf.z; kT[d + 3][t] = kf.w;
    }
    if (tid < DH) {
        qT[tid][49] = 0.f; qT[tid][50] = 0.f; qT[tid][51] = 0.f;
        kT[tid][49] = 0.f; kT[tid][50] = 0.f; kT[tid][51] = 0.f;
    }
    for (int idx = tid; idx < 169; idx += 256) poss[idx] = pos[idx];
    __syncthreads();

    const bool m_ul = (w >= NWIN - N2);                                          // 56..63
    const bool m_lr = (w >= NWIN - N1 - 1) && ((w - (NWIN - N1 - 1)) % N1 == 0); // {55,63}
    const float NEG = -1e30f;
    const float scale = 0.17677669529663687f;  // 1/sqrt(32)

    // Pass 1: dots 4x4 micro-tile per thread (13 i-chunks x 13 j-chunks = 169)
    if (tid < 169) {
        int ic = tid / 13, jc = tid % 13;
        int i0 = ic * 4, j0 = jc * 4;
        u64 acc2[4][2] = {};
        #pragma unroll
        for (int d = 0; d < DH; d++) {
            float4 qf = *(const float4*)&qT[d][i0];
            ulonglong2 k2 = *(const ulonglong2*)&kT[d][j0];
            float qa[4] = {qf.x, qf.y, qf.z, qf.w};
            #pragma unroll
            for (int ii = 0; ii < 4; ii++) {
                u64 q2 = pack_dup(qa[ii]);
                fma2(acc2[ii][0], q2, k2.x);
                fma2(acc2[ii][1], q2, k2.y);
            }
        }
        #pragma unroll
        for (int ii = 0; ii < 4; ii++) {
            int i = i0 + ii;
            if (i < PP) {
                float2 p0 = unpack2(acc2[ii][0]), p1 = unpack2(acc2[ii][1]);
                float sv[4] = {p0.x, p0.y, p1.x, p1.y};
                int iy = i / PW, ix = i % PW;
                float outv[4];
                float cm = -3.4e38f;
                #pragma unroll
                for (int jj = 0; jj < 4; jj++) {
                    int j = j0 + jj;
                    float val = NEG;
                    if (j < PP) {
                        int jy = j / PW, jx = j % PW;
                        val = sv[jj] * scale + poss[(jy - iy + 6) * 13 + (jx - ix + 6)];
                        if (m_ul && ((iy >= 4) != (jy >= 4))) val = NEG;
                        if (m_lr && ((ix >= 4) != (jx >= 4))) val = NEG;
                        cm = fmaxf(cm, val);
                    }
                    outv[jj] = val;
                }
                *(float4*)&dots[i][j0] = make_float4(outv[0], outv[1], outv[2], outv[3]);
                cpart[i][jc] = cm;
            }
        }
    }
    __syncthreads();

    if (tid < PP) {
        float m = cpart[tid][0];
        #pragma unroll
        for (int c = 1; c < 13; c++) m = fmaxf(m, cpart[tid][c]);
        rowm[tid] = m;
    }
    __syncthreads();

    // Pass 2: exp + per-chunk sum (637 items)
    for (int idx = tid; idx < PP * 13; idx += 256) {
        int i = idx / 13, jc = idx % 13, j0 = jc * 4;
        float m = rowm[i];
        float4 dv = *(const float4*)&dots[i][j0];
        float xv[4] = {dv.x, dv.y, dv.z, dv.w};
        float ev[4];
        float ps = 0.f;
        #pragma unroll
        for (int jj = 0; jj < 4; jj++) {
            float e = (j0 + jj < PP) ? __expf(xv[jj] - m) : 0.f;
            ev[jj] = e;
            ps += e;
        }
        *(float4*)&dots[i][j0] = make_float4(ev[0], ev[1], ev[2], ev[3]);
        cpart[i][jc] = ps;
    }
    __syncthreads();

    if (tid < PP) {
        float s = 0.f;
        #pragma unroll
        for (int c = 0; c < 13; c++) s += cpart[tid][c];
        rowinv[tid] = 1.0f / s;
    }
    __syncthreads();

    // Overlapped final phase:
    //   threads 0..103   : attn @ v (4x4 micro-tile over i,d)
    //   threads 104..255 : normalized attn tensor write
    if (tid < 104) {
        int ic = tid / 8, dc = tid % 8;
        int i0 = ic * 4, d0 = dc * 4;
        float* ob = g_att + (size_t)(bi * NWIN + w) * PP * INNER + head * DH;
        u64 acc2[4][2] = {};
        #pragma unroll
        for (int j = 0; j < PP; j++) {
            ulonglong2 v2 = *(const ulonglong2*)&v[j][d0];
            #pragma unroll
            for (int ii = 0; ii < 4; ii++) {
                u64 p2 = pack_dup(dots[i0 + ii][j]);
                fma2(acc2[ii][0], p2, v2.x);
                fma2(acc2[ii][1], p2, v2.y);
            }
        }
        #pragma unroll
        for (int ii = 0; ii < 4; ii++) {
            int i = i0 + ii;
            if (i < PP) {
                u64 r2 = pack_dup(rowinv[i]);
                ulonglong2 o2;
                mul2(o2.x, acc2[ii][0], r2);
                mul2(o2.y, acc2[ii][1], r2);
                *(ulonglong2*)&ob[(size_t)i * INNER + d0] = o2;
            }
        }
    } else {
        float* ao = attn_out + (size_t)bid * (PP * PP);
        for (int idx = tid - 104; idx < PP * PP; idx += 152) {
            int i = idx / PP, j = idx % PP;
            ao[idx] = dots[i][j] * rowinv[i];
        }
    }
}

// ---------------------------------------------------------------------------
// Kernel 3: out = g_att @ w_out + b_out, smem-staged coalesced scatter
// grid = (n-tiles, m-tiles): g_att L2 reuse across the 2 n-tiles
// ---------------------------------------------------------------------------
__global__ void __launch_bounds__(256) out_gemm(const float* __restrict__ wout,
                                                const float* __restrict__ bout,
                                                float* __restrict__ out) {
    __shared__ union U {
        struct { float As[16][128]; float Bs[16][128]; } mm;
        float sbuf[128][129];
        __device__ U() {}
    } sh;
    __shared__ int   rowoff[128];
    __shared__ float bout_s[128];

    const int m0  = blockIdx.y * 128;
    const int n0  = blockIdx.x * 128;
    const int tid = threadIdx.x;

    if (tid < 128) {
        rowoff[tid] = row_to_off(m0 + tid);
        bout_s[tid] = bout[n0 + tid];
    }
    __syncthreads();

    const int lm  = tid & 127;
    const int lk0 = tid >> 7;
    const int tr  = TR_OF(tid);
    const int tc  = TC_OF(tid);

    u64 acc2[8][4] = {};

    for (int k0 = 0; k0 < INNER; k0 += 16) {
        #pragma unroll
        for (int i = 0; i < 8; i++) {
            int kk = lk0 + 2 * i;
            sh.mm.As[kk][lm] = g_att[(size_t)(m0 + lm) * INNER + k0 + kk];
            sh.mm.Bs[kk][lm] = wout[(k0 + kk) * DIM + n0 + lm];
        }
        __syncthreads();
        #pragma unroll
        for (int k = 0; k < 16; k++) {
            float a[8];
            *(float4*)(a)     = *(const float4*)&sh.mm.As[k][tr];
            *(float4*)(a + 4) = *(const float4*)&sh.mm.As[k][tr + 4];
            u64 b2[4];
            *(ulonglong2*)(b2)     = *(const ulonglong2*)&sh.mm.Bs[k][tc];
            *(ulonglong2*)(b2 + 2) = *(const ulonglong2*)&sh.mm.Bs[k][tc + 4];
            #pragma unroll
            for (int i = 0; i < 8; i++) {
                u64 a2 = pack_dup(a[i]);
                #pragma unroll
                for (int jp = 0; jp < 4; jp++)
                    fma2(acc2[i][jp], a2, b2[jp]);
            }
        }
        __syncthreads();
    }

    // stage tile into smem (row stride 129 -> conflict-free column reads)
    #pragma unroll
    for (int i = 0; i < 8; i++) {
        #pragma unroll
        for (int jp = 0; jp < 4; jp++) {
            float2 p = unpack2(acc2[i][jp]);
            sh.sbuf[tr + i][tc + 2 * jp]     = p.x;
            sh.sbuf[tr + i][tc + 2 * jp + 1] = p.y;
        }
    }
    __syncthreads();

    // scatter: consecutive threads sweep m (7-contiguous runs in w)
    #pragma unroll
    for (int it = 0; it < 64; it++) {
        int flat = it * 256 + tid;
        int m = flat & 127;
        int c = flat >> 7;
        out[rowoff[m] + (n0 + c) * SP] = sh.sbuf[m][c] + bout_s[c];
    }
}

// ---------------------------------------------------------------------------
extern "C" void kernel_launch(void* const* d_in, const int* in_sizes, int n_in,
                              void* d_out, int out_size) {
    const float* x    = (const float*)d_in[0];
    const float* pos  = (const float*)d_in[1];
    const float* wqkv = (const float*)d_in[2];
    const float* wout = (const float*)d_in[3];
    const float* bout = (const float*)d_in[4];

    float* out      = (float*)d_out;
    float* attn_out = out + (size_t)BATCH * DIM * SP;

    dim3 g1(QKV_N / 128, M_TOTAL / 128);   // n fastest -> x reused in L2
    qkv_gemm<<<g1, 256>>>(x, wqkv);

    attn_kernel<<<BATCH * NWIN * HEADS, 256>>>(pos, attn_out);

    dim3 g3(DIM / 128, M_TOTAL / 128);     // n fastest -> g_att reused in L2
    out_gemm<<<g3, 256>>>(wout, bout, out);
}

// round 10
// speedup vs baseline: 1.7764x; 1.1891x over previous
#include <cuda_runtime.h>
#include <cstdint>

#define BATCH 32
#define DIM   256
#define HW    56
#define SP    (HW*HW)        // 3136
#define PW    7
#define PP    49
#define DD    3
#define N1    8
#define N2    8
#define NWIN  64
#define HEADS 8
#define DH    32
#define INNER 256
#define QKV_N 768
#define M_TOTAL (BATCH*NWIN*PP)   // 100352

__device__ float g_qkv[(size_t)M_TOTAL * QKV_N];   // ~308 MB
__device__ float g_att[(size_t)M_TOTAL * INNER];   // ~103 MB

typedef unsigned long long u64;

__device__ __forceinline__ u64 pack_dup(float x) {
    u64 r; unsigned u = __float_as_uint(x);
    asm("mov.b64 %0, {%1, %1};" : "=l"(r) : "r"(u));
    return r;
}
__device__ __forceinline__ void fma2(u64& d, u64 a, u64 b) {
    asm("fma.rn.f32x2 %0, %1, %2, %0;" : "+l"(d) : "l"(a), "l"(b));
}
__device__ __forceinline__ void mul2(u64& d, u64 a, u64 b) {
    asm("mul.rn.f32x2 %0, %1, %2;" : "=l"(d) : "l"(a), "l"(b));
}
__device__ __forceinline__ float2 unpack2(u64 v) {
    unsigned lo, hi;
    asm("mov.b64 {%0, %1}, %2;" : "=r"(lo), "=r"(hi) : "l"(v));
    return make_float2(__uint_as_float(lo), __uint_as_float(hi));
}
__device__ __forceinline__ uint32_t f2tf32(float f) {
    uint32_t r; asm("cvt.rna.tf32.f32 %0, %1;" : "=r"(r) : "f"(f)); return r;
}
__device__ __forceinline__ void mma_tf32(float* d, const uint32_t* a, const uint32_t* b) {
    asm volatile(
        "mma.sync.aligned.m16n8k8.row.col.f32.tf32.tf32.f32 "
        "{%0,%1,%2,%3}, {%4,%5,%6,%7}, {%8,%9}, {%0,%1,%2,%3};"
        : "+f"(d[0]), "+f"(d[1]), "+f"(d[2]), "+f"(d[3])
        : "r"(a[0]), "r"(a[1]), "r"(a[2]), "r"(a[3]), "r"(b[0]), "r"(b[1]));
}

__device__ __forceinline__ int row_to_off(int r) {
    int bi  = r / (NWIN * PP);
    int rem = r % (NWIN * PP);
    int w   = rem / PP;
    int t   = rem % PP;
    int n1i = w / N2, n2i = w % N2;
    int py  = t / PW, px  = t % PW;
    int hh  = (n1i * PW + py + DD) % HW;
    int ww  = (n2i * PW + px + DD) % HW;
    return bi * DIM * SP + hh * HW + ww;
}

// ---------------------------------------------------------------------------
// Kernel 1: qkv = window(roll(x)) @ w_qkv — tf32 mma.sync m16n8k8
// 128x128 CTA tile, 8 warps (2m x 4n), warp tile 64x32
// ---------------------------------------------------------------------------
__global__ void __launch_bounds__(256) qkv_gemm(const float* __restrict__ x,
                                                const float* __restrict__ wqkv) {
    __shared__ uint32_t As[16][132];   // pad 4 -> fragment LDS conflict-free
    __shared__ uint32_t Bs[16][132];
    __shared__ int rowoff[128];

    const int m0  = blockIdx.y * 128;
    const int n0  = blockIdx.x * 128;
    const int tid = threadIdx.x;

    if (tid < 128) rowoff[tid] = row_to_off(m0 + tid);
    __syncthreads();

    const int lm   = tid & 127;
    const int lk0  = tid >> 7;       // 0..1
    const int lane = tid & 31;
    const int wid  = tid >> 5;       // 0..7
    const int mb   = (wid & 1) * 64; // warp m base within tile
    const int nb   = (wid >> 1) * 32;
    const int tg   = lane >> 2;      // groupID (row / col)
    const int tq   = lane & 3;       // thread-in-group (k)

    float d[4][4][4] = {};           // [m-atom][n-atom][frag]

    for (int k0 = 0; k0 < DIM; k0 += 16) {
        #pragma unroll
        for (int i = 0; i < 8; i++) {
            int kk = lk0 + 2 * i;
            As[kk][lm] = f2tf32(x[rowoff[lm] + (k0 + kk) * SP]);
            Bs[kk][lm] = f2tf32(wqkv[(k0 + kk) * QKV_N + n0 + lm]);
        }
        __syncthreads();
        #pragma unroll
        for (int s = 0; s < 2; s++) {
            uint32_t a[4][4], b[4][2];
            #pragma unroll
            for (int am = 0; am < 4; am++) {
                int r = mb + am * 16 + tg;
                a[am][0] = As[s * 8 + tq][r];
                a[am][1] = As[s * 8 + tq][r + 8];
                a[am][2] = As[s * 8 + tq + 4][r];
                a[am][3] = As[s * 8 + tq + 4][r + 8];
            }
            #pragma unroll
            for (int an = 0; an < 4; an++) {
                int c = nb + an * 8 + tg;
                b[an][0] = Bs[s * 8 + tq][c];
                b[an][1] = Bs[s * 8 + tq + 4][c];
            }
            #pragma unroll
            for (int am = 0; am < 4; am++)
                #pragma unroll
                for (int an = 0; an < 4; an++)
                    mma_tf32(d[am][an], a[am], b[an]);
        }
        __syncthreads();
    }

    // epilogue: d0,d1 -> row tg, cols 2tq,2tq+1; d2,d3 -> row tg+8
    #pragma unroll
    for (int am = 0; am < 4; am++) {
        size_t r0 = (size_t)(m0 + mb + am * 16 + tg) * QKV_N;
        size_t r1 = r0 + 8 * QKV_N;
        #pragma unroll
        for (int an = 0; an < 4; an++) {
            int c = n0 + nb + an * 8 + 2 * tq;
            *(float2*)&g_qkv[r0 + c] = make_float2(d[am][an][0], d[am][an][1]);
            *(float2*)&g_qkv[r1 + c] = make_float2(d[am][an][2], d[am][an][3]);
        }
    }
}

// ---------------------------------------------------------------------------
// Kernel 2: per (b, window, head) attention (unchanged, passing R7 version)
// ---------------------------------------------------------------------------
__global__ void __launch_bounds__(256) attn_kernel(const float* __restrict__ pos,
                                                   float* __restrict__ attn_out) {
    const int bid  = blockIdx.x;
    const int head = bid % HEADS;
    const int bw   = bid / HEADS;
    const int w    = bw % NWIN;
    const int bi   = bw / NWIN;
    const int tid  = threadIdx.x;

    __shared__ float qT[DH][52];
    __shared__ float kT[DH][52];
    __shared__ float v[PP][DH];
    __shared__ float dots[PP][56];
    __shared__ float poss[169];
    __shared__ float cpart[PP][13];
    __shared__ float rowm[PP], rowinv[PP];

    const float* base = g_qkv + (size_t)(bi * NWIN + w) * PP * QKV_N + head * DH;
    for (int idx = tid; idx < PP * 8; idx += 256) {
        int t = idx >> 3, c = idx & 7;
        const float* rowp = base + (size_t)t * QKV_N + c * 4;
        float4 qf = *(const float4*)(rowp);
        float4 kf = *(const float4*)(rowp + INNER);
        float4 vf = *(const float4*)(rowp + 2 * INNER);
        *(float4*)&v[t][c * 4] = vf;
        int d = c * 4;
        qT[d][t] = qf.x; qT[d + 1][t] = qf.y; qT[d + 2][t] = qf.z; qT[d + 3][t] = qf.w;
        kT[d][t] = kf.x; kT[d + 1][t] = kf.y; kT[d + 2][t] = kf.z; kT[d + 3][t] = kf.w;
    }
    if (tid < DH) {
        qT[tid][49] = 0.f; qT[tid][50] = 0.f; qT[tid][51] = 0.f;
        kT[tid][49] = 0.f; kT[tid][50] = 0.f; kT[tid][51] = 0.f;
    }
    for (int idx = tid; idx < 169; idx += 256) poss[idx] = pos[idx];
    __syncthreads();

    const bool m_ul = (w >= NWIN - N2);
    const bool m_lr = (w >= NWIN - N1 - 1) && ((w - (NWIN - N1 - 1)) % N1 == 0);
    const float NEG = -1e30f;
    const float scale = 0.17677669529663687f;

    if (tid < 169) {
        int ic = tid / 13, jc = tid % 13;
        int i0 = ic * 4, j0 = jc * 4;
        u64 acc2[4][2] = {};
        #pragma unroll
        for (int d = 0; d < DH; d++) {
            float4 qf = *(const float4*)&qT[d][i0];
            ulonglong2 k2 = *(const ulonglong2*)&kT[d][j0];
            float qa[4] = {qf.x, qf.y, qf.z, qf.w};
            #pragma unroll
            for (int ii = 0; ii < 4; ii++) {
                u64 q2 = pack_dup(qa[ii]);
                fma2(acc2[ii][0], q2, k2.x);
                fma2(acc2[ii][1], q2, k2.y);
            }
        }
        #pragma unroll
        for (int ii = 0; ii < 4; ii++) {
            int i = i0 + ii;
            if (i < PP) {
                float2 p0 = unpack2(acc2[ii][0]), p1 = unpack2(acc2[ii][1]);
                float sv[4] = {p0.x, p0.y, p1.x, p1.y};
                int iy = i / PW, ix = i % PW;
                float outv[4];
                float cm = -3.4e38f;
                #pragma unroll
                for (int jj = 0; jj < 4; jj++) {
                    int j = j0 + jj;
                    float val = NEG;
                    if (j < PP) {
                        int jy = j / PW, jx = j % PW;
                        val = sv[jj] * scale + poss[(jy - iy + 6) * 13 + (jx - ix + 6)];
                        if (m_ul && ((iy >= 4) != (jy >= 4))) val = NEG;
                        if (m_lr && ((ix >= 4) != (jx >= 4))) val = NEG;
                        cm = fmaxf(cm, val);
                    }
                    outv[jj] = val;
                }
                *(float4*)&dots[i][j0] = make_float4(outv[0], outv[1], outv[2], outv[3]);
                cpart[i][jc] = cm;
            }
        }
    }
    __syncthreads();

    if (tid < PP) {
        float m = cpart[tid][0];
        #pragma unroll
        for (int c = 1; c < 13; c++) m = fmaxf(m, cpart[tid][c]);
        rowm[tid] = m;
    }
    __syncthreads();

    for (int idx = tid; idx < PP * 13; idx += 256) {
        int i = idx / 13, jc = idx % 13, j0 = jc * 4;
        float m = rowm[i];
        float4 dv = *(const float4*)&dots[i][j0];
        float xv[4] = {dv.x, dv.y, dv.z, dv.w};
        float ev[4];
        float ps = 0.f;
        #pragma unroll
        for (int jj = 0; jj < 4; jj++) {
            float e = (j0 + jj < PP) ? __expf(xv[jj] - m) : 0.f;
            ev[jj] = e;
            ps += e;
        }
        *(float4*)&dots[i][j0] = make_float4(ev[0], ev[1], ev[2], ev[3]);
        cpart[i][jc] = ps;
    }
    __syncthreads();

    if (tid < PP) {
        float s = 0.f;
        #pragma unroll
        for (int c = 0; c < 13; c++) s += cpart[tid][c];
        rowinv[tid] = 1.0f / s;
    }
    __syncthreads();

    if (tid < 104) {
        int ic = tid / 8, dc = tid % 8;
        int i0 = ic * 4, d0 = dc * 4;
        float* ob = g_att + (size_t)(bi * NWIN + w) * PP * INNER + head * DH;
        u64 acc2[4][2] = {};
        #pragma unroll
        for (int j = 0; j < PP; j++) {
            ulonglong2 v2 = *(const ulonglong2*)&v[j][d0];
            #pragma unroll
            for (int ii = 0; ii < 4; ii++) {
                u64 p2 = pack_dup(dots[i0 + ii][j]);
                fma2(acc2[ii][0], p2, v2.x);
                fma2(acc2[ii][1], p2, v2.y);
            }
        }
        #pragma unroll
        for (int ii = 0; ii < 4; ii++) {
            int i = i0 + ii;
            if (i < PP) {
                u64 r2 = pack_dup(rowinv[i]);
                ulonglong2 o2;
                mul2(o2.x, acc2[ii][0], r2);
                mul2(o2.y, acc2[ii][1], r2);
                *(ulonglong2*)&ob[(size_t)i * INNER + d0] = o2;
            }
        }
    } else {
        float* ao = attn_out + (size_t)bid * (PP * PP);
        for (int idx = tid - 104; idx < PP * PP; idx += 152) {
            int i = idx / PP, j = idx % PP;
            ao[idx] = dots[i][j] * rowinv[i];
        }
    }
}

// conflict-free lane mapping for fp32 GEMM (kernel 3)
#define TR_OF(tid) ((((tid) >> 5) & 3) * 32 + ((tid) & 3) * 8)
#define TC_OF(tid) ((((tid) >> 7)) * 64 + ((((tid) & 31) >> 2)) * 8)

// ---------------------------------------------------------------------------
// Kernel 3: out = g_att @ w_out + b_out (unchanged, passing R7 version)
// ---------------------------------------------------------------------------
__global__ void __launch_bounds__(256) out_gemm(const float* __restrict__ wout,
                                                const float* __restrict__ bout,
                                                float* __restrict__ out) {
    __shared__ union U {
        struct { float As[16][128]; float Bs[16][128]; } mm;
        float sbuf[128][129];
        __device__ U() {}
    } sh;
    __shared__ int   rowoff[128];
    __shared__ float bout_s[128];

    const int m0  = blockIdx.y * 128;
    const int n0  = blockIdx.x * 128;
    const int tid = threadIdx.x;

    if (tid < 128) {
        rowoff[tid] = row_to_off(m0 + tid);
        bout_s[tid] = bout[n0 + tid];
    }
    __syncthreads();

    const int lm  = tid & 127;
    const int lk0 = tid >> 7;
    const int tr  = TR_OF(tid);
    const int tc  = TC_OF(tid);

    u64 acc2[8][4] = {};

    for (int k0 = 0; k0 < INNER; k0 += 16) {
        #pragma unroll
        for (int i = 0; i < 8; i++) {
            int kk = lk0 + 2 * i;
            sh.mm.As[kk][lm] = g_att[(size_t)(m0 + lm) * INNER + k0 + kk];
            sh.mm.Bs[kk][lm] = wout[(k0 + kk) * DIM + n0 + lm];
        }
        __syncthreads();
        #pragma unroll
        for (int k = 0; k < 16; k++) {
            float a[8];
            *(float4*)(a)     = *(const float4*)&sh.mm.As[k][tr];
            *(float4*)(a + 4) = *(const float4*)&sh.mm.As[k][tr + 4];
            u64 b2[4];
            *(ulonglong2*)(b2)     = *(const ulonglong2*)&sh.mm.Bs[k][tc];
            *(ulonglong2*)(b2 + 2) = *(const ulonglong2*)&sh.mm.Bs[k][tc + 4];
            #pragma unroll
            for (int i = 0; i < 8; i++) {
                u64 a2 = pack_dup(a[i]);
                #pragma unroll
                for (int jp = 0; jp < 4; jp++)
                    fma2(acc2[i][jp], a2, b2[jp]);
            }
        }
        __syncthreads();
    }

    #pragma unroll
    for (int i = 0; i < 8; i++) {
        #pragma unroll
        for (int jp = 0; jp < 4; jp++) {
            float2 p = unpack2(acc2[i][jp]);
            sh.sbuf[tr + i][tc + 2 * jp]     = p.x;
            sh.sbuf[tr + i][tc + 2 * jp + 1] = p.y;
        }
    }
    __syncthreads();

    #pragma unroll
    for (int it = 0; it < 64; it++) {
        int flat = it * 256 + tid;
        int m = flat & 127;
        int c = flat >> 7;
        out[rowoff[m] + (n0 + c) * SP] = sh.sbuf[m][c] + bout_s[c];
    }
}

// ---------------------------------------------------------------------------
extern "C" void kernel_launch(void* const* d_in, const int* in_sizes, int n_in,
                              void* d_out, int out_size) {
    const float* x    = (const float*)d_in[0];
    const float* pos  = (const float*)d_in[1];
    const float* wqkv = (const float*)d_in[2];
    const float* wout = (const float*)d_in[3];
    const float* bout = (const float*)d_in[4];

    float* out      = (float*)d_out;
    float* attn_out = out + (size_t)BATCH * DIM * SP;

    dim3 g1(QKV_N / 128, M_TOTAL / 128);   // n fastest -> x reused in L2
    qkv_gemm<<<g1, 256>>>(x, wqkv);

    attn_kernel<<<BATCH * NWIN * HEADS, 256>>>(pos, attn_out);

    dim3 g3(DIM / 128, M_TOTAL / 128);     // n fastest -> g_att reused in L2
    out_gemm<<<g3, 256>>>(wout, bout, out);
}

// round 11
// speedup vs baseline: 2.3327x; 1.3132x over previous
#include <cuda_runtime.h>
#include <cstdint>

#define BATCH 32
#define DIM   256
#define HW    56
#define SP    (HW*HW)        // 3136
#define PW    7
#define PP    49
#define DD    3
#define N1    8
#define N2    8
#define NWIN  64
#define HEADS 8
#define DH    32
#define INNER 256
#define QKV_N 768
#define M_TOTAL (BATCH*NWIN*PP)   // 100352

__device__ float g_qkv[(size_t)M_TOTAL * QKV_N];   // ~308 MB
__device__ float g_att[(size_t)M_TOTAL * INNER];   // ~103 MB

typedef unsigned long long u64;

__device__ __forceinline__ u64 pack_dup(float x) {
    u64 r; unsigned u = __float_as_uint(x);
    asm("mov.b64 %0, {%1, %1};" : "=l"(r) : "r"(u));
    return r;
}
__device__ __forceinline__ void fma2(u64& d, u64 a, u64 b) {
    asm("fma.rn.f32x2 %0, %1, %2, %0;" : "+l"(d) : "l"(a), "l"(b));
}
__device__ __forceinline__ void mul2(u64& d, u64 a, u64 b) {
    asm("mul.rn.f32x2 %0, %1, %2;" : "=l"(d) : "l"(a), "l"(b));
}
__device__ __forceinline__ float2 unpack2(u64 v) {
    unsigned lo, hi;
    asm("mov.b64 {%0, %1}, %2;" : "=r"(lo), "=r"(hi) : "l"(v));
    return make_float2(__uint_as_float(lo), __uint_as_float(hi));
}
__device__ __forceinline__ uint32_t f2tf32(float f) {
    uint32_t r; asm("cvt.rna.tf32.f32 %0, %1;" : "=r"(r) : "f"(f)); return r;
}
__device__ __forceinline__ void mma_tf32(float* d, const uint32_t* a, const uint32_t* b) {
    asm volatile(
        "mma.sync.aligned.m16n8k8.row.col.f32.tf32.tf32.f32 "
        "{%0,%1,%2,%3}, {%4,%5,%6,%7}, {%8,%9}, {%0,%1,%2,%3};"
        : "+f"(d[0]), "+f"(d[1]), "+f"(d[2]), "+f"(d[3])
        : "r"(a[0]), "r"(a[1]), "r"(a[2]), "r"(a[3]), "r"(b[0]), "r"(b[1]));
}

__device__ __forceinline__ int row_to_off(int r) {
    int bi  = r / (NWIN * PP);
    int rem = r % (NWIN * PP);
    int w   = rem / PP;
    int t   = rem % PP;
    int n1i = w / N2, n2i = w % N2;
    int py  = t / PW, px  = t % PW;
    int hh  = (n1i * PW + py + DD) % HW;
    int ww  = (n2i * PW + px + DD) % HW;
    return bi * DIM * SP + hh * HW + ww;
}

// ---------------------------------------------------------------------------
// Kernel 1: qkv = window(roll(x)) @ w_qkv — tf32 mma.sync, double-buffered
// 128x128 CTA tile, 8 warps (2m x 4n), warp tile 64x32
// ---------------------------------------------------------------------------
__global__ void __launch_bounds__(256, 2) qkv_gemm(const float* __restrict__ x,
                                                   const float* __restrict__ wqkv) {
    __shared__ uint32_t As[2][16][132];   // pad 4 -> fragment LDS conflict-free
    __shared__ uint32_t Bs[2][16][132];
    __shared__ int rowoff[128];

    const int m0  = blockIdx.y * 128;
    const int n0  = blockIdx.x * 128;
    const int tid = threadIdx.x;

    if (tid < 128) rowoff[tid] = row_to_off(m0 + tid);
    __syncthreads();

    const int lm   = tid & 127;
    const int lk0  = tid >> 7;       // 0..1
    const int lane = tid & 31;
    const int wid  = tid >> 5;       // 0..7
    const int mb   = (wid & 1) * 64;
    const int nb   = (wid >> 1) * 32;
    const int tg   = lane >> 2;
    const int tq   = lane & 3;

    const float* arow = x + rowoff[lm];
    const float* brow = wqkv + n0 + lm;

    float d[4][4][4] = {};
    float a_reg[8], b_reg[8];

    // preload + stage chunk 0
    #pragma unroll
    for (int i = 0; i < 8; i++) {
        int kk = lk0 + 2 * i;
        a_reg[i] = arow[kk * SP];
        b_reg[i] = brow[kk * QKV_N];
    }
    #pragma unroll
    for (int i = 0; i < 8; i++) {
        int kk = lk0 + 2 * i;
        As[0][kk][lm] = f2tf32(a_reg[i]);
        Bs[0][kk][lm] = f2tf32(b_reg[i]);
    }
    __syncthreads();

    for (int c = 0; c < 16; c++) {
        const int cur = c & 1;
        const int k0  = c * 16;
        if (c < 15) {
            #pragma unroll
            for (int i = 0; i < 8; i++) {
                int kk = k0 + 16 + lk0 + 2 * i;
                a_reg[i] = arow[kk * SP];
                b_reg[i] = brow[kk * QKV_N];
            }
        }
        #pragma unroll
        for (int s = 0; s < 2; s++) {
            uint32_t a[4][4], b[4][2];
            #pragma unroll
            for (int am = 0; am < 4; am++) {
                int r = mb + am * 16 + tg;
                a[am][0] = As[cur][s * 8 + tq][r];
                a[am][1] = As[cur][s * 8 + tq][r + 8];
                a[am][2] = As[cur][s * 8 + tq + 4][r];
                a[am][3] = As[cur][s * 8 + tq + 4][r + 8];
            }
            #pragma unroll
            for (int an = 0; an < 4; an++) {
                int cc = nb + an * 8 + tg;
                b[an][0] = Bs[cur][s * 8 + tq][cc];
                b[an][1] = Bs[cur][s * 8 + tq + 4][cc];
            }
            #pragma unroll
            for (int am = 0; am < 4; am++)
                #pragma unroll
                for (int an = 0; an < 4; an++)
                    mma_tf32(d[am][an], a[am], b[an]);
        }
        if (c < 15) {
            const int nxt = cur ^ 1;
            #pragma unroll
            for (int i = 0; i < 8; i++) {
                int kk = lk0 + 2 * i;
                As[nxt][kk][lm] = f2tf32(a_reg[i]);
                Bs[nxt][kk][lm] = f2tf32(b_reg[i]);
            }
        }
        __syncthreads();
    }

    #pragma unroll
    for (int am = 0; am < 4; am++) {
        size_t r0 = (size_t)(m0 + mb + am * 16 + tg) * QKV_N;
        size_t r1 = r0 + 8 * QKV_N;
        #pragma unroll
        for (int an = 0; an < 4; an++) {
            int c = n0 + nb + an * 8 + 2 * tq;
            *(float2*)&g_qkv[r0 + c] = make_float2(d[am][an][0], d[am][an][1]);
            *(float2*)&g_qkv[r1 + c] = make_float2(d[am][an][2], d[am][an][3]);
        }
    }
}

// ---------------------------------------------------------------------------
// Kernel 2: per (b, window, head) attention (unchanged, passing R7 version)
// ---------------------------------------------------------------------------
__global__ void __launch_bounds__(256) attn_kernel(const float* __restrict__ pos,
                                                   float* __restrict__ attn_out) {
    const int bid  = blockIdx.x;
    const int head = bid % HEADS;
    const int bw   = bid / HEADS;
    const int w    = bw % NWIN;
    const int bi   = bw / NWIN;
    const int tid  = threadIdx.x;

    __shared__ float qT[DH][52];
    __shared__ float kT[DH][52];
    __shared__ float v[PP][DH];
    __shared__ float dots[PP][56];
    __shared__ float poss[169];
    __shared__ float cpart[PP][13];
    __shared__ float rowm[PP], rowinv[PP];

    const float* base = g_qkv + (size_t)(bi * NWIN + w) * PP * QKV_N + head * DH;
    for (int idx = tid; idx < PP * 8; idx += 256) {
        int t = idx >> 3, c = idx & 7;
        const float* rowp = base + (size_t)t * QKV_N + c * 4;
        float4 qf = *(const float4*)(rowp);
        float4 kf = *(const float4*)(rowp + INNER);
        float4 vf = *(const float4*)(rowp + 2 * INNER);
        *(float4*)&v[t][c * 4] = vf;
        int d = c * 4;
        qT[d][t] = qf.x; qT[d + 1][t] = qf.y; qT[d + 2][t] = qf.z; qT[d + 3][t] = qf.w;
        kT[d][t] = kf.x; kT[d + 1][t] = kf.y; kT[d + 2][t] = kf.z; kT[d + 3][t] = kf.w;
    }
    if (tid < DH) {
        qT[tid][49] = 0.f; qT[tid][50] = 0.f; qT[tid][51] = 0.f;
        kT[tid][49] = 0.f; kT[tid][50] = 0.f; kT[tid][51] = 0.f;
    }
    for (int idx = tid; idx < 169; idx += 256) poss[idx] = pos[idx];
    __syncthreads();

    const bool m_ul = (w >= NWIN - N2);
    const bool m_lr = (w >= NWIN - N1 - 1) && ((w - (NWIN - N1 - 1)) % N1 == 0);
    const float NEG = -1e30f;
    const float scale = 0.17677669529663687f;

    if (tid < 169) {
        int ic = tid / 13, jc = tid % 13;
        int i0 = ic * 4, j0 = jc * 4;
        u64 acc2[4][2] = {};
        #pragma unroll
        for (int d = 0; d < DH; d++) {
            float4 qf = *(const float4*)&qT[d][i0];
            ulonglong2 k2 = *(const ulonglong2*)&kT[d][j0];
            float qa[4] = {qf.x, qf.y, qf.z, qf.w};
            #pragma unroll
            for (int ii = 0; ii < 4; ii++) {
                u64 q2 = pack_dup(qa[ii]);
                fma2(acc2[ii][0], q2, k2.x);
                fma2(acc2[ii][1], q2, k2.y);
            }
        }
        #pragma unroll
        for (int ii = 0; ii < 4; ii++) {
            int i = i0 + ii;
            if (i < PP) {
                float2 p0 = unpack2(acc2[ii][0]), p1 = unpack2(acc2[ii][1]);
                float sv[4] = {p0.x, p0.y, p1.x, p1.y};
                int iy = i / PW, ix = i % PW;
                float outv[4];
                float cm = -3.4e38f;
                #pragma unroll
                for (int jj = 0; jj < 4; jj++) {
                    int j = j0 + jj;
                    float val = NEG;
                    if (j < PP) {
                        int jy = j / PW, jx = j % PW;
                        val = sv[jj] * scale + poss[(jy - iy + 6) * 13 + (jx - ix + 6)];
                        if (m_ul && ((iy >= 4) != (jy >= 4))) val = NEG;
                        if (m_lr && ((ix >= 4) != (jx >= 4))) val = NEG;
                        cm = fmaxf(cm, val);
                    }
                    outv[jj] = val;
                }
                *(float4*)&dots[i][j0] = make_float4(outv[0], outv[1], outv[2], outv[3]);
                cpart[i][jc] = cm;
            }
        }
    }
    __syncthreads();

    if (tid < PP) {
        float m = cpart[tid][0];
        #pragma unroll
        for (int c = 1; c < 13; c++) m = fmaxf(m, cpart[tid][c]);
        rowm[tid] = m;
    }
    __syncthreads();

    for (int idx = tid; idx < PP * 13; idx += 256) {
        int i = idx / 13, jc = idx % 13, j0 = jc * 4;
        float m = rowm[i];
        float4 dv = *(const float4*)&dots[i][j0];
        float xv[4] = {dv.x, dv.y, dv.z, dv.w};
        float ev[4];
        float ps = 0.f;
        #pragma unroll
        for (int jj = 0; jj < 4; jj++) {
            float e = (j0 + jj < PP) ? __expf(xv[jj] - m) : 0.f;
            ev[jj] = e;
            ps += e;
        }
        *(float4*)&dots[i][j0] = make_float4(ev[0], ev[1], ev[2], ev[3]);
        cpart[i][jc] = ps;
    }
    __syncthreads();

    if (tid < PP) {
        float s = 0.f;
        #pragma unroll
        for (int c = 0; c < 13; c++) s += cpart[tid][c];
        rowinv[tid] = 1.0f / s;
    }
    __syncthreads();

    if (tid < 104) {
        int ic = tid / 8, dc = tid % 8;
        int i0 = ic * 4, d0 = dc * 4;
        float* ob = g_att + (size_t)(bi * NWIN + w) * PP * INNER + head * DH;
        u64 acc2[4][2] = {};
        #pragma unroll
        for (int j = 0; j < PP; j++) {
            ulonglong2 v2 = *(const ulonglong2*)&v[j][d0];
            #pragma unroll
            for (int ii = 0; ii < 4; ii++) {
                u64 p2 = pack_dup(dots[i0 + ii][j]);
                fma2(acc2[ii][0], p2, v2.x);
                fma2(acc2[ii][1], p2, v2.y);
            }
        }
        #pragma unroll
        for (int ii = 0; ii < 4; ii++) {
            int i = i0 + ii;
            if (i < PP) {
                u64 r2 = pack_dup(rowinv[i]);
                ulonglong2 o2;
                mul2(o2.x, acc2[ii][0], r2);
                mul2(o2.y, acc2[ii][1], r2);
                *(ulonglong2*)&ob[(size_t)i * INNER + d0] = o2;
            }
        }
    } else {
        float* ao = attn_out + (size_t)bid * (PP * PP);
        for (int idx = tid - 104; idx < PP * PP; idx += 152) {
            int i = idx / PP, j = idx % PP;
            ao[idx] = dots[i][j] * rowinv[i];
        }
    }
}

// ---------------------------------------------------------------------------
// Kernel 3: out = g_att @ w_out + b_out — tf32 mma.sync + staged scatter
// ---------------------------------------------------------------------------
__global__ void __launch_bounds__(256) out_gemm(const float* __restrict__ wout,
                                                const float* __restrict__ bout,
                                                float* __restrict__ out) {
    __shared__ union U {
        struct { uint32_t As[16][132]; uint32_t Bs[16][132]; } mm;
        float sbuf[128][129];
        __device__ U() {}
    } sh;
    __shared__ int   rowoff[128];
    __shared__ float bout_s[128];

    const int m0  = blockIdx.y * 128;
    const int n0  = blockIdx.x * 128;
    const int tid = threadIdx.x;

    if (tid < 128) {
        rowoff[tid] = row_to_off(m0 + tid);
        bout_s[tid] = bout[n0 + tid];
    }
    __syncthreads();

    const int lm   = tid & 127;
    const int lk0  = tid >> 7;
    const int lane = tid & 31;
    const int wid  = tid >> 5;
    const int mb   = (wid & 1) * 64;
    const int nb   = (wid >> 1) * 32;
    const int tg   = lane >> 2;
    const int tq   = lane & 3;

    const int am_  = tid >> 1;            // A-load row (0..127)
    const int kb_  = (tid & 1) * 8;       // A-load k base (0 or 8)
    const float* arow = &g_att[(size_t)(m0 + am_) * INNER + kb_];

    float d[4][4][4] = {};

    for (int k0 = 0; k0 < INNER; k0 += 16) {
        // A: contiguous float4 pairs per thread
        float4 a0 = *(const float4*)(arow + k0);
        float4 a1 = *(const float4*)(arow + k0 + 4);
        sh.mm.As[kb_ + 0][am_] = f2tf32(a0.x);
        sh.mm.As[kb_ + 1][am_] = f2tf32(a0.y);
        sh.mm.As[kb_ + 2][am_] = f2tf32(a0.z);
        sh.mm.As[kb_ + 3][am_] = f2tf32(a0.w);
        sh.mm.As[kb_ + 4][am_] = f2tf32(a1.x);
        sh.mm.As[kb_ + 5][am_] = f2tf32(a1.y);
        sh.mm.As[kb_ + 6][am_] = f2tf32(a1.z);
        sh.mm.As[kb_ + 7][am_] = f2tf32(a1.w);
        // B: coalesced over n
        #pragma unroll
        for (int i = 0; i < 8; i++) {
            int kk = lk0 + 2 * i;
            sh.mm.Bs[kk][lm] = f2tf32(wout[(k0 + kk) * DIM + n0 + lm]);
        }
        __syncthreads();
        #pragma unroll
        for (int s = 0; s < 2; s++) {
            uint32_t a[4][4], b[4][2];
            #pragma unroll
            for (int am = 0; am < 4; am++) {
                int r = mb + am * 16 + tg;
                a[am][0] = sh.mm.As[s * 8 + tq][r];
                a[am][1] = sh.mm.As[s * 8 + tq][r + 8];
                a[am][2] = sh.mm.As[s * 8 + tq + 4][r];
                a[am][3] = sh.mm.As[s * 8 + tq + 4][r + 8];
            }
            #pragma unroll
            for (int an = 0; an < 4; an++) {
                int cc = nb + an * 8 + tg;
                b[an][0] = sh.mm.Bs[s * 8 + tq][cc];
                b[an][1] = sh.mm.Bs[s * 8 + tq + 4][cc];
            }
            #pragma unroll
            for (int am = 0; am < 4; am++)
                #pragma unroll
                for (int an = 0; an < 4; an++)
                    mma_tf32(d[am][an], a[am], b[an]);
        }
        __syncthreads();
    }

    // stage tile into smem (stride 129 -> conflict-free)
    #pragma unroll
    for (int am = 0; am < 4; am++) {
        int r0 = mb + am * 16 + tg;
        #pragma unroll
        for (int an = 0; an < 4; an++) {
            int c = nb + an * 8 + 2 * tq;
            sh.sbuf[r0][c]     = d[am][an][0];
            sh.sbuf[r0][c + 1] = d[am][an][1];
            sh.sbuf[r0 + 8][c]     = d[am][an][2];
            sh.sbuf[r0 + 8][c + 1] = d[am][an][3];
        }
    }
    __syncthreads();

    // scatter: consecutive threads sweep m (7-contiguous runs in w)
    #pragma unroll
    for (int it = 0; it < 64; it++) {
        int flat = it * 256 + tid;
        int m = flat & 127;
        int c = flat >> 7;
        out[rowoff[m] + (n0 + c) * SP] = sh.sbuf[m][c] + bout_s[c];
    }
}

// ---------------------------------------------------------------------------
extern "C" void kernel_launch(void* const* d_in, const int* in_sizes, int n_in,
                              void* d_out, int out_size) {
    const float* x    = (const float*)d_in[0];
    const float* pos  = (const float*)d_in[1];
    const float* wqkv = (const float*)d_in[2];
    const float* wout = (const float*)d_in[3];
    const float* bout = (const float*)d_in[4];

    float* out      = (float*)d_out;
    float* attn_out = out + (size_t)BATCH * DIM * SP;

    dim3 g1(QKV_N / 128, M_TOTAL / 128);   // n fastest -> x reused in L2
    qkv_gemm<<<g1, 256>>>(x, wqkv);

    attn_kernel<<<BATCH * NWIN * HEADS, 256>>>(pos, attn_out);

    dim3 g3(DIM / 128, M_TOTAL / 128);     // n fastest -> g_att reused in L2
    out_gemm<<<g3, 256>>>(wout, bout, out);
}

// round 12
// speedup vs baseline: 2.6077x; 1.1179x over previous
#include <cuda_runtime.h>
#include <cstdint>

#define BATCH 32
#define DIM   256
#define HW    56
#define SP    (HW*HW)        // 3136
#define PW    7
#define PP    49
#define DD    3
#define N1    8
#define N2    8
#define NWIN  64
#define HEADS 8
#define DH    32
#define INNER 256
#define QKV_N 768
#define M_TOTAL (BATCH*NWIN*PP)   // 100352

#define PADW 136   // 136 mod 32 == 8 -> fragment LDS bank = 8*tq + tg (bijective)

__device__ float g_qkv[(size_t)M_TOTAL * QKV_N];   // ~308 MB
__device__ float g_att[(size_t)M_TOTAL * INNER];   // ~103 MB

typedef unsigned long long u64;

__device__ __forceinline__ u64 pack_dup(float x) {
    u64 r; unsigned u = __float_as_uint(x);
    asm("mov.b64 %0, {%1, %1};" : "=l"(r) : "r"(u));
    return r;
}
__device__ __forceinline__ void fma2(u64& d, u64 a, u64 b) {
    asm("fma.rn.f32x2 %0, %1, %2, %0;" : "+l"(d) : "l"(a), "l"(b));
}
__device__ __forceinline__ void mul2(u64& d, u64 a, u64 b) {
    asm("mul.rn.f32x2 %0, %1, %2;" : "=l"(d) : "l"(a), "l"(b));
}
__device__ __forceinline__ float2 unpack2(u64 v) {
    unsigned lo, hi;
    asm("mov.b64 {%0, %1}, %2;" : "=r"(lo), "=r"(hi) : "l"(v));
    return make_float2(__uint_as_float(lo), __uint_as_float(hi));
}
__device__ __forceinline__ uint32_t f2tf32(float f) {
    uint32_t r; asm("cvt.rna.tf32.f32 %0, %1;" : "=r"(r) : "f"(f)); return r;
}
__device__ __forceinline__ void mma_tf32(float* d, const uint32_t* a, const uint32_t* b) {
    asm volatile(
        "mma.sync.aligned.m16n8k8.row.col.f32.tf32.tf32.f32 "
        "{%0,%1,%2,%3}, {%4,%5,%6,%7}, {%8,%9}, {%0,%1,%2,%3};"
        : "+f"(d[0]), "+f"(d[1]), "+f"(d[2]), "+f"(d[3])
        : "r"(a[0]), "r"(a[1]), "r"(a[2]), "r"(a[3]), "r"(b[0]), "r"(b[1]));
}

__device__ __forceinline__ int row_to_off(int r) {
    int bi  = r / (NWIN * PP);
    int rem = r % (NWIN * PP);
    int w   = rem / PP;
    int t   = rem % PP;
    int n1i = w / N2, n2i = w % N2;
    int py  = t / PW, px  = t % PW;
    int hh  = (n1i * PW + py + DD) % HW;
    int ww  = (n2i * PW + px + DD) % HW;
    return bi * DIM * SP + hh * HW + ww;
}

// ---------------------------------------------------------------------------
// Kernel 1: qkv = window(roll(x)) @ w_qkv — tf32 mma.sync, double-buffered
// 128x128 CTA tile, 8 warps (2m x 4n), warp tile 64x32
// ---------------------------------------------------------------------------
__global__ void __launch_bounds__(256, 2) qkv_gemm(const float* __restrict__ x,
                                                   const float* __restrict__ wqkv) {
    __shared__ uint32_t As[2][16][PADW];
    __shared__ uint32_t Bs[2][16][PADW];
    __shared__ int rowoff[128];

    const int m0  = blockIdx.y * 128;
    const int n0  = blockIdx.x * 128;
    const int tid = threadIdx.x;

    if (tid < 128) rowoff[tid] = row_to_off(m0 + tid);
    __syncthreads();

    const int lm   = tid & 127;
    const int lk0  = tid >> 7;       // 0..1
    const int lane = tid & 31;
    const int wid  = tid >> 5;       // 0..7
    const int mb   = (wid & 1) * 64;
    const int nb   = (wid >> 1) * 32;
    const int tg   = lane >> 2;
    const int tq   = lane & 3;

    const float* arow = x + rowoff[lm];
    const float* brow = wqkv + n0 + lm;

    float d[4][4][4] = {};
    float a_reg[8], b_reg[8];

    #pragma unroll
    for (int i = 0; i < 8; i++) {
        int kk = lk0 + 2 * i;
        a_reg[i] = arow[kk * SP];
        b_reg[i] = brow[kk * QKV_N];
    }
    #pragma unroll
    for (int i = 0; i < 8; i++) {
        int kk = lk0 + 2 * i;
        As[0][kk][lm] = f2tf32(a_reg[i]);
        Bs[0][kk][lm] = f2tf32(b_reg[i]);
    }
    __syncthreads();

    for (int c = 0; c < 16; c++) {
        const int cur = c & 1;
        const int k0  = c * 16;
        if (c < 15) {
            #pragma unroll
            for (int i = 0; i < 8; i++) {
                int kk = k0 + 16 + lk0 + 2 * i;
                a_reg[i] = arow[kk * SP];
                b_reg[i] = brow[kk * QKV_N];
            }
        }
        #pragma unroll
        for (int s = 0; s < 2; s++) {
            uint32_t a[4][4], b[4][2];
            #pragma unroll
            for (int am = 0; am < 4; am++) {
                int r = mb + am * 16 + tg;
                a[am][0] = As[cur][s * 8 + tq][r];
                a[am][1] = As[cur][s * 8 + tq][r + 8];
                a[am][2] = As[cur][s * 8 + tq + 4][r];
                a[am][3] = As[cur][s * 8 + tq + 4][r + 8];
            }
            #pragma unroll
            for (int an = 0; an < 4; an++) {
                int cc = nb + an * 8 + tg;
                b[an][0] = Bs[cur][s * 8 + tq][cc];
                b[an][1] = Bs[cur][s * 8 + tq + 4][cc];
            }
            #pragma unroll
            for (int am = 0; am < 4; am++)
                #pragma unroll
                for (int an = 0; an < 4; an++)
                    mma_tf32(d[am][an], a[am], b[an]);
        }
        if (c < 15) {
            const int nxt = cur ^ 1;
            #pragma unroll
            for (int i = 0; i < 8; i++) {
                int kk = lk0 + 2 * i;
                As[nxt][kk][lm] = f2tf32(a_reg[i]);
                Bs[nxt][kk][lm] = f2tf32(b_reg[i]);
            }
        }
        __syncthreads();
    }

    #pragma unroll
    for (int am = 0; am < 4; am++) {
        size_t r0 = (size_t)(m0 + mb + am * 16 + tg) * QKV_N;
        size_t r1 = r0 + 8 * QKV_N;
        #pragma unroll
        for (int an = 0; an < 4; an++) {
            int c = n0 + nb + an * 8 + 2 * tq;
            *(float2*)&g_qkv[r0 + c] = make_float2(d[am][an][0], d[am][an][1]);
            *(float2*)&g_qkv[r1 + c] = make_float2(d[am][an][2], d[am][an][3]);
        }
    }
}

// ---------------------------------------------------------------------------
// Kernel 2: per (b, window, head) attention (unchanged, passing R7 version)
// ---------------------------------------------------------------------------
__global__ void __launch_bounds__(256) attn_kernel(const float* __restrict__ pos,
                                                   float* __restrict__ attn_out) {
    const int bid  = blockIdx.x;
    const int head = bid % HEADS;
    const int bw   = bid / HEADS;
    const int w    = bw % NWIN;
    const int bi   = bw / NWIN;
    const int tid  = threadIdx.x;

    __shared__ float qT[DH][52];
    __shared__ float kT[DH][52];
    __shared__ float v[PP][DH];
    __shared__ float dots[PP][56];
    __shared__ float poss[169];
    __shared__ float cpart[PP][13];
    __shared__ float rowm[PP], rowinv[PP];

    const float* base = g_qkv + (size_t)(bi * NWIN + w) * PP * QKV_N + head * DH;
    for (int idx = tid; idx < PP * 8; idx += 256) {
        int t = idx >> 3, c = idx & 7;
        const float* rowp = base + (size_t)t * QKV_N + c * 4;
        float4 qf = *(const float4*)(rowp);
        float4 kf = *(const float4*)(rowp + INNER);
        float4 vf = *(const float4*)(rowp + 2 * INNER);
        *(float4*)&v[t][c * 4] = vf;
        int d = c * 4;
        qT[d][t] = qf.x; qT[d + 1][t] = qf.y; qT[d + 2][t] = qf.z; qT[d + 3][t] = qf.w;
        kT[d][t] = kf.x; kT[d + 1][t] = kf.y; kT[d + 2][t] = kf.z; kT[d + 3][t] = kf.w;
    }
    if (tid < DH) {
        qT[tid][49] = 0.f; qT[tid][50] = 0.f; qT[tid][51] = 0.f;
        kT[tid][49] = 0.f; kT[tid][50] = 0.f; kT[tid][51] = 0.f;
    }
    for (int idx = tid; idx < 169; idx += 256) poss[idx] = pos[idx];
    __syncthreads();

    const bool m_ul = (w >= NWIN - N2);
    const bool m_lr = (w >= NWIN - N1 - 1) && ((w - (NWIN - N1 - 1)) % N1 == 0);
    const float NEG = -1e30f;
    const float scale = 0.17677669529663687f;

    if (tid < 169) {
        int ic = tid / 13, jc = tid % 13;
        int i0 = ic * 4, j0 = jc * 4;
        u64 acc2[4][2] = {};
        #pragma unroll
        for (int d = 0; d < DH; d++) {
            float4 qf = *(const float4*)&qT[d][i0];
            ulonglong2 k2 = *(const ulonglong2*)&kT[d][j0];
            float qa[4] = {qf.x, qf.y, qf.z, qf.w};
            #pragma unroll
            for (int ii = 0; ii < 4; ii++) {
                u64 q2 = pack_dup(qa[ii]);
                fma2(acc2[ii][0], q2, k2.x);
                fma2(acc2[ii][1], q2, k2.y);
            }
        }
        #pragma unroll
        for (int ii = 0; ii < 4; ii++) {
            int i = i0 + ii;
            if (i < PP) {
                float2 p0 = unpack2(acc2[ii][0]), p1 = unpack2(acc2[ii][1]);
                float sv[4] = {p0.x, p0.y, p1.x, p1.y};
                int iy = i / PW, ix = i % PW;
                float outv[4];
                float cm = -3.4e38f;
                #pragma unroll
                for (int jj = 0; jj < 4; jj++) {
                    int j = j0 + jj;
                    float val = NEG;
                    if (j < PP) {
                        int jy = j / PW, jx = j % PW;
                        val = sv[jj] * scale + poss[(jy - iy + 6) * 13 + (jx - ix + 6)];
                        if (m_ul && ((iy >= 4) != (jy >= 4))) val = NEG;
                        if (m_lr && ((ix >= 4) != (jx >= 4))) val = NEG;
                        cm = fmaxf(cm, val);
                    }
                    outv[jj] = val;
                }
                *(float4*)&dots[i][j0] = make_float4(outv[0], outv[1], outv[2], outv[3]);
                cpart[i][jc] = cm;
            }
        }
    }
    __syncthreads();

    if (tid < PP) {
        float m = cpart[tid][0];
        #pragma unroll
        for (int c = 1; c < 13; c++) m = fmaxf(m, cpart[tid][c]);
        rowm[tid] = m;
    }
    __syncthreads();

    for (int idx = tid; idx < PP * 13; idx += 256) {
        int i = idx / 13, jc = idx % 13, j0 = jc * 4;
        float m = rowm[i];
        float4 dv = *(const float4*)&dots[i][j0];
        float xv[4] = {dv.x, dv.y, dv.z, dv.w};
        float ev[4];
        float ps = 0.f;
        #pragma unroll
        for (int jj = 0; jj < 4; jj++) {
            float e = (j0 + jj < PP) ? __expf(xv[jj] - m) : 0.f;
            ev[jj] = e;
            ps += e;
        }
        *(float4*)&dots[i][j0] = make_float4(ev[0], ev[1], ev[2], ev[3]);
        cpart[i][jc] = ps;
    }
    __syncthreads();

    if (tid < PP) {
        float s = 0.f;
        #pragma unroll
        for (int c = 0; c < 13; c++) s += cpart[tid][c];
        rowinv[tid] = 1.0f / s;
    }
    __syncthreads();

    if (tid < 104) {
        int ic = tid / 8, dc = tid % 8;
        int i0 = ic * 4, d0 = dc * 4;
        float* ob = g_att + (size_t)(bi * NWIN + w) * PP * INNER + head * DH;
        u64 acc2[4][2] = {};
        #pragma unroll
        for (int j = 0; j < PP; j++) {
            ulonglong2 v2 = *(const ulonglong2*)&v[j][d0];
            #pragma unroll
            for (int ii = 0; ii < 4; ii++) {
                u64 p2 = pack_dup(dots[i0 + ii][j]);
                fma2(acc2[ii][0], p2, v2.x);
                fma2(acc2[ii][1], p2, v2.y);
            }
        }
        #pragma unroll
        for (int ii = 0; ii < 4; ii++) {
            int i = i0 + ii;
            if (i < PP) {
                u64 r2 = pack_dup(rowinv[i]);
                ulonglong2 o2;
                mul2(o2.x, acc2[ii][0], r2);
                mul2(o2.y, acc2[ii][1], r2);
                *(ulonglong2*)&ob[(size_t)i * INNER + d0] = o2;
            }
        }
    } else {
        float* ao = attn_out + (size_t)bid * (PP * PP);
        for (int idx = tid - 104; idx < PP * PP; idx += 152) {
            int i = idx / PP, j = idx % PP;
            ao[idx] = dots[i][j] * rowinv[i];
        }
    }
}

// ---------------------------------------------------------------------------
// Kernel 3: out = g_att @ w_out + b_out — tf32 mma.sync + staged scatter
// ---------------------------------------------------------------------------
__global__ void __launch_bounds__(256) out_gemm(const float* __restrict__ wout,
                                                const float* __restrict__ bout,
                                                float* __restrict__ out) {
    __shared__ union U {
        struct { uint32_t As[16][PADW]; uint32_t Bs[16][PADW]; } mm;
        float sbuf[128][129];
        __device__ U() {}
    } sh;
    __shared__ int   rowoff[128];
    __shared__ float bout_s[128];

    const int m0  = blockIdx.y * 128;
    const int n0  = blockIdx.x * 128;
    const int tid = threadIdx.x;

    if (tid < 128) {
        rowoff[tid] = row_to_off(m0 + tid);
        bout_s[tid] = bout[n0 + tid];
    }
    __syncthreads();

    const int lm   = tid & 127;
    const int lk0  = tid >> 7;
    const int lane = tid & 31;
    const int wid  = tid >> 5;
    const int mb   = (wid & 1) * 64;
    const int nb   = (wid >> 1) * 32;
    const int tg   = lane >> 2;
    const int tq   = lane & 3;

    const int am_  = tid >> 1;
    const int kb_  = (tid & 1) * 8;
    const float* arow = &g_att[(size_t)(m0 + am_) * INNER + kb_];

    float d[4][4][4] = {};

    for (int k0 = 0; k0 < INNER; k0 += 16) {
        float4 a0 = *(const float4*)(arow + k0);
        float4 a1 = *(const float4*)(arow + k0 + 4);
        sh.mm.As[kb_ + 0][am_] = f2tf32(a0.x);
        sh.mm.As[kb_ + 1][am_] = f2tf32(a0.y);
        sh.mm.As[kb_ + 2][am_] = f2tf32(a0.z);
        sh.mm.As[kb_ + 3][am_] = f2tf32(a0.w);
        sh.mm.As[kb_ + 4][am_] = f2tf32(a1.x);
        sh.mm.As[kb_ + 5][am_] = f2tf32(a1.y);
        sh.mm.As[kb_ + 6][am_] = f2tf32(a1.z);
        sh.mm.As[kb_ + 7][am_] = f2tf32(a1.w);
        #pragma unroll
        for (int i = 0; i < 8; i++) {
            int kk = lk0 + 2 * i;
            sh.mm.Bs[kk][lm] = f2tf32(wout[(k0 + kk) * DIM + n0 + lm]);
        }
        __syncthreads();
        #pragma unroll
        for (int s = 0; s < 2; s++) {
            uint32_t a[4][4], b[4][2];
            #pragma unroll
            for (int am = 0; am < 4; am++) {
                int r = mb + am * 16 + tg;
                a[am][0] = sh.mm.As[s * 8 + tq][r];
                a[am][1] = sh.mm.As[s * 8 + tq][r + 8];
                a[am][2] = sh.mm.As[s * 8 + tq + 4][r];
                a[am][3] = sh.mm.As[s * 8 + tq + 4][r + 8];
            }
            #pragma unroll
            for (int an = 0; an < 4; an++) {
                int cc = nb + an * 8 + tg;
                b[an][0] = sh.mm.Bs[s * 8 + tq][cc];
                b[an][1] = sh.mm.Bs[s * 8 + tq + 4][cc];
            }
            #pragma unroll
            for (int am = 0; am < 4; am++)
                #pragma unroll
                for (int an = 0; an < 4; an++)
                    mma_tf32(d[am][an], a[am], b[an]);
        }
        __syncthreads();
    }

    #pragma unroll
    for (int am = 0; am < 4; am++) {
        int r0 = mb + am * 16 + tg;
        #pragma unroll
        for (int an = 0; an < 4; an++) {
            int c = nb + an * 8 + 2 * tq;
            sh.sbuf[r0][c]     = d[am][an][0];
            sh.sbuf[r0][c + 1] = d[am][an][1];
            sh.sbuf[r0 + 8][c]     = d[am][an][2];
            sh.sbuf[r0 + 8][c + 1] = d[am][an][3];
        }
    }
    __syncthreads();

    #pragma unroll
    for (int it = 0; it < 64; it++) {
        int flat = it * 256 + tid;
        int m = flat & 127;
        int c = flat >> 7;
        out[rowoff[m] + (n0 + c) * SP] = sh.sbuf[m][c] + bout_s[c];
    }
}

// ---------------------------------------------------------------------------
extern "C" void kernel_launch(void* const* d_in, const int* in_sizes, int n_in,
                              void* d_out, int out_size) {
    const float* x    = (const float*)d_in[0];
    const float* pos  = (const float*)d_in[1];
    const float* wqkv = (const float*)d_in[2];
    const float* wout = (const float*)d_in[3];
    const float* bout = (const float*)d_in[4];

    float* out      = (float*)d_out;
    float* attn_out = out + (size_t)BATCH * DIM * SP;

    dim3 g1(QKV_N / 128, M_TOTAL / 128);   // n fastest -> x reused in L2
    qkv_gemm<<<g1, 256>>>(x, wqkv);

    attn_kernel<<<BATCH * NWIN * HEADS, 256>>>(pos, attn_out);

    dim3 g3(DIM / 128, M_TOTAL / 128);     // n fastest -> g_att reused in L2
    out_gemm<<<g3, 256>>>(wout, bout, out);
}

// round 13
// speedup vs baseline: 2.7862x; 1.0685x over previous
#include <cuda_runtime.h>
#include <cstdint>

#define BATCH 32
#define DIM   256
#define HW    56
#define SP    (HW*HW)        // 3136
#define PW    7
#define PP    49
#define DD    3
#define N1    8
#define N2    8
#define NWIN  64
#define HEADS 8
#define DH    32
#define INNER 256
#define QKV_N 768
#define M_TOTAL (BATCH*NWIN*PP)   // 100352

#define PADW 136   // 136 mod 32 == 8 -> fragment LDS bank = 8*tq + tg (bijective)

__device__ float    g_qkv[(size_t)M_TOTAL * QKV_N];    // ~308 MB
__device__ uint32_t g_att32[(size_t)M_TOTAL * INNER];  // tf32 bits, ~103 MB
__device__ uint32_t g_wqkv32[DIM * QKV_N];             // prepped tf32 weights
__device__ uint32_t g_wout32[INNER * DIM];

typedef unsigned long long u64;

__device__ __forceinline__ u64 pack_dup(float x) {
    u64 r; unsigned u = __float_as_uint(x);
    asm("mov.b64 %0, {%1, %1};" : "=l"(r) : "r"(u));
    return r;
}
__device__ __forceinline__ void fma2(u64& d, u64 a, u64 b) {
    asm("fma.rn.f32x2 %0, %1, %2, %0;" : "+l"(d) : "l"(a), "l"(b));
}
__device__ __forceinline__ void mul2(u64& d, u64 a, u64 b) {
    asm("mul.rn.f32x2 %0, %1, %2;" : "=l"(d) : "l"(a), "l"(b));
}
__device__ __forceinline__ float2 unpack2(u64 v) {
    unsigned lo, hi;
    asm("mov.b64 {%0, %1}, %2;" : "=r"(lo), "=r"(hi) : "l"(v));
    return make_float2(__uint_as_float(lo), __uint_as_float(hi));
}
__device__ __forceinline__ uint32_t f2tf32(float f) {
    uint32_t r; asm("cvt.rna.tf32.f32 %0, %1;" : "=r"(r) : "f"(f)); return r;
}
__device__ __forceinline__ void mma_tf32(float* d, const uint32_t* a, const uint32_t* b) {
    asm volatile(
        "mma.sync.aligned.m16n8k8.row.col.f32.tf32.tf32.f32 "
        "{%0,%1,%2,%3}, {%4,%5,%6,%7}, {%8,%9}, {%0,%1,%2,%3};"
        : "+f"(d[0]), "+f"(d[1]), "+f"(d[2]), "+f"(d[3])
        : "r"(a[0]), "r"(a[1]), "r"(a[2]), "r"(a[3]), "r"(b[0]), "r"(b[1]));
}

__device__ __forceinline__ int row_to_off(int r) {
    int bi  = r / (NWIN * PP);
    int rem = r % (NWIN * PP);
    int w   = rem / PP;
    int t   = rem % PP;
    int n1i = w / N2, n2i = w % N2;
    int py  = t / PW, px  = t % PW;
    int hh  = (n1i * PW + py + DD) % HW;
    int ww  = (n2i * PW + px + DD) % HW;
    return bi * DIM * SP + hh * HW + ww;
}

// ---------------------------------------------------------------------------
// Kernel 0: pre-convert weights to tf32 bits
// ---------------------------------------------------------------------------
__global__ void prep_w(const float* __restrict__ wqkv, const float* __restrict__ wout) {
    const int t1 = DIM * QKV_N;            // 196608
    const int t2 = INNER * DIM;            // 65536
    for (int i = blockIdx.x * blockDim.x + threadIdx.x; i < t1 + t2;
         i += gridDim.x * blockDim.x) {
        if (i < t1) g_wqkv32[i] = f2tf32(wqkv[i]);
        else        g_wout32[i - t1] = f2tf32(wout[i - t1]);
    }
}

// ---------------------------------------------------------------------------
// Kernel 1: qkv GEMM — tf32 mma.sync, 128x128 tile, 4 warps of 64x64,
// double-buffered, 2 CTAs/SM
// ---------------------------------------------------------------------------
__global__ void __launch_bounds__(128, 2) qkv_gemm(const float* __restrict__ x) {
    __shared__ uint32_t As[2][16][PADW];
    __shared__ uint32_t Bs[2][16][PADW];

    const int m0  = blockIdx.y * 128;
    const int n0  = blockIdx.x * 128;
    const int tid = threadIdx.x;

    const int lane = tid & 31;
    const int wid  = tid >> 5;       // 0..3
    const int mb   = (wid & 1) * 64;
    const int nb   = (wid >> 1) * 64;
    const int tg   = lane >> 2;
    const int tq   = lane & 3;

    const float*    arow = x + row_to_off(m0 + tid);
    const uint32_t* brow = g_wqkv32 + n0 + tid;

    float d[4][8][4] = {};
    float    a_reg[16];
    uint32_t b_reg[16];

    #pragma unroll
    for (int i = 0; i < 16; i++) {
        a_reg[i] = arow[i * SP];
        b_reg[i] = brow[i * QKV_N];
    }
    #pragma unroll
    for (int i = 0; i < 16; i++) {
        As[0][i][tid] = f2tf32(a_reg[i]);
        Bs[0][i][tid] = b_reg[i];
    }
    __syncthreads();

    for (int c = 0; c < 16; c++) {
        const int cur = c & 1;
        if (c < 15) {
            const int kb = (c + 1) * 16;
            #pragma unroll
            for (int i = 0; i < 16; i++) {
                a_reg[i] = arow[(kb + i) * SP];
                b_reg[i] = brow[(kb + i) * QKV_N];
            }
        }
        #pragma unroll
        for (int s = 0; s < 2; s++) {
            uint32_t a[4][4], b[8][2];
            #pragma unroll
            for (int am = 0; am < 4; am++) {
                int r = mb + am * 16 + tg;
                a[am][0] = As[cur][s * 8 + tq][r];
                a[am][1] = As[cur][s * 8 + tq][r + 8];
                a[am][2] = As[cur][s * 8 + tq + 4][r];
                a[am][3] = As[cur][s * 8 + tq + 4][r + 8];
            }
            #pragma unroll
            for (int an = 0; an < 8; an++) {
                int cc = nb + an * 8 + tg;
                b[an][0] = Bs[cur][s * 8 + tq][cc];
                b[an][1] = Bs[cur][s * 8 + tq + 4][cc];
            }
            #pragma unroll
            for (int am = 0; am < 4; am++)
                #pragma unroll
                for (int an = 0; an < 8; an++)
                    mma_tf32(d[am][an], a[am], b[an]);
        }
        if (c < 15) {
            const int nxt = cur ^ 1;
            #pragma unroll
            for (int i = 0; i < 16; i++) {
                As[nxt][i][tid] = f2tf32(a_reg[i]);
                Bs[nxt][i][tid] = b_reg[i];
            }
        }
        __syncthreads();
    }

    #pragma unroll
    for (int am = 0; am < 4; am++) {
        size_t r0 = (size_t)(m0 + mb + am * 16 + tg) * QKV_N;
        size_t r1 = r0 + 8 * QKV_N;
        #pragma unroll
        for (int an = 0; an < 8; an++) {
            int c = n0 + nb + an * 8 + 2 * tq;
            *(float2*)&g_qkv[r0 + c] = make_float2(d[am][an][0], d[am][an][1]);
            *(float2*)&g_qkv[r1 + c] = make_float2(d[am][an][2], d[am][an][3]);
        }
    }
}

// ---------------------------------------------------------------------------
// Kernel 2: per (b, window, head) attention (R7 logic; g_att stored as tf32)
// ---------------------------------------------------------------------------
__global__ void __launch_bounds__(256) attn_kernel(const float* __restrict__ pos,
                                                   float* __restrict__ attn_out) {
    const int bid  = blockIdx.x;
    const int head = bid % HEADS;
    const int bw   = bid / HEADS;
    const int w    = bw % NWIN;
    const int bi   = bw / NWIN;
    const int tid  = threadIdx.x;

    __shared__ float qT[DH][52];
    __shared__ float kT[DH][52];
    __shared__ float v[PP][DH];
    __shared__ float dots[PP][56];
    __shared__ float poss[169];
    __shared__ float cpart[PP][13];
    __shared__ float rowm[PP], rowinv[PP];

    const float* base = g_qkv + (size_t)(bi * NWIN + w) * PP * QKV_N + head * DH;
    for (int idx = tid; idx < PP * 8; idx += 256) {
        int t = idx >> 3, c = idx & 7;
        const float* rowp = base + (size_t)t * QKV_N + c * 4;
        float4 qf = *(const float4*)(rowp);
        float4 kf = *(const float4*)(rowp + INNER);
        float4 vf = *(const float4*)(rowp + 2 * INNER);
        *(float4*)&v[t][c * 4] = vf;
        int d = c * 4;
        qT[d][t] = qf.x; qT[d + 1][t] = qf.y; qT[d + 2][t] = qf.z; qT[d + 3][t] = qf.w;
        kT[d][t] = kf.x; kT[d + 1][t] = kf.y; kT[d + 2][t] = kf.z; kT[d + 3][t] = kf.w;
    }
    if (tid < DH) {
        qT[tid][49] = 0.f; qT[tid][50] = 0.f; qT[tid][51] = 0.f;
        kT[tid][49] = 0.f; kT[tid][50] = 0.f; kT[tid][51] = 0.f;
    }
    for (int idx = tid; idx < 169; idx += 256) poss[idx] = pos[idx];
    __syncthreads();

    const bool m_ul = (w >= NWIN - N2);
    const bool m_lr = (w >= NWIN - N1 - 1) && ((w - (NWIN - N1 - 1)) % N1 == 0);
    const float NEG = -1e30f;
    const float scale = 0.17677669529663687f;

    if (tid < 169) {
        int ic = tid / 13, jc = tid % 13;
        int i0 = ic * 4, j0 = jc * 4;
        u64 acc2[4][2] = {};
        #pragma unroll
        for (int d = 0; d < DH; d++) {
            float4 qf = *(const float4*)&qT[d][i0];
            ulonglong2 k2 = *(const ulonglong2*)&kT[d][j0];
            float qa[4] = {qf.x, qf.y, qf.z, qf.w};
            #pragma unroll
            for (int ii = 0; ii < 4; ii++) {
                u64 q2 = pack_dup(qa[ii]);
                fma2(acc2[ii][0], q2, k2.x);
                fma2(acc2[ii][1], q2, k2.y);
            }
        }
        #pragma unroll
        for (int ii = 0; ii < 4; ii++) {
            int i = i0 + ii;
            if (i < PP) {
                float2 p0 = unpack2(acc2[ii][0]), p1 = unpack2(acc2[ii][1]);
                float sv[4] = {p0.x, p0.y, p1.x, p1.y};
                int iy = i / PW, ix = i % PW;
                float outv[4];
                float cm = -3.4e38f;
                #pragma unroll
                for (int jj = 0; jj < 4; jj++) {
                    int j = j0 + jj;
                    float val = NEG;
                    if (j < PP) {
                        int jy = j / PW, jx = j % PW;
                        val = sv[jj] * scale + poss[(jy - iy + 6) * 13 + (jx - ix + 6)];
                        if (m_ul && ((iy >= 4) != (jy >= 4))) val = NEG;
                        if (m_lr && ((ix >= 4) != (jx >= 4))) val = NEG;
                        cm = fmaxf(cm, val);
                    }
                    outv[jj] = val;
                }
                *(float4*)&dots[i][j0] = make_float4(outv[0], outv[1], outv[2], outv[3]);
                cpart[i][jc] = cm;
            }
        }
    }
    __syncthreads();

    if (tid < PP) {
        float m = cpart[tid][0];
        #pragma unroll
        for (int c = 1; c < 13; c++) m = fmaxf(m, cpart[tid][c]);
        rowm[tid] = m;
    }
    __syncthreads();

    for (int idx = tid; idx < PP * 13; idx += 256) {
        int i = idx / 13, jc = idx % 13, j0 = jc * 4;
        float m = rowm[i];
        float4 dv = *(const float4*)&dots[i][j0];
        float xv[4] = {dv.x, dv.y, dv.z, dv.w};
        float ev[4];
        float ps = 0.f;
        #pragma unroll
        for (int jj = 0; jj < 4; jj++) {
            float e = (j0 + jj < PP) ? __expf(xv[jj] - m) : 0.f;
            ev[jj] = e;
            ps += e;
        }
        *(float4*)&dots[i][j0] = make_float4(ev[0], ev[1], ev[2], ev[3]);
        cpart[i][jc] = ps;
    }
    __syncthreads();

    if (tid < PP) {
        float s = 0.f;
        #pragma unroll
        for (int c = 0; c < 13; c++) s += cpart[tid][c];
        rowinv[tid] = 1.0f / s;
    }
    __syncthreads();

    if (tid < 104) {
        int ic = tid / 8, dc = tid % 8;
        int i0 = ic * 4, d0 = dc * 4;
        uint32_t* ob = g_att32 + (size_t)(bi * NWIN + w) * PP * INNER + head * DH;
        u64 acc2[4][2] = {};
        #pragma unroll
        for (int j = 0; j < PP; j++) {
            ulonglong2 v2 = *(const ulonglong2*)&v[j][d0];
            #pragma unroll
            for (int ii = 0; ii < 4; ii++) {
                u64 p2 = pack_dup(dots[i0 + ii][j]);
                fma2(acc2[ii][0], p2, v2.x);
                fma2(acc2[ii][1], p2, v2.y);
            }
        }
        #pragma unroll
        for (int ii = 0; ii < 4; ii++) {
            int i = i0 + ii;
            if (i < PP) {
                u64 r2 = pack_dup(rowinv[i]);
                ulonglong2 o2;
                mul2(o2.x, acc2[ii][0], r2);
                mul2(o2.y, acc2[ii][1], r2);
                float2 p0 = unpack2(o2.x), p1 = unpack2(o2.y);
                uint4 uo;
                uo.x = f2tf32(p0.x); uo.y = f2tf32(p0.y);
                uo.z = f2tf32(p1.x); uo.w = f2tf32(p1.y);
                *(uint4*)&ob[(size_t)i * INNER + d0] = uo;
            }
        }
    } else {
        float* ao = attn_out + (size_t)bid * (PP * PP);
        for (int idx = tid - 104; idx < PP * PP; idx += 152) {
            int i = idx / PP, j = idx % PP;
            ao[idx] = dots[i][j] * rowinv[i];
        }
    }
}

// ---------------------------------------------------------------------------
// Kernel 3: out = g_att @ w_out + b_out — 4 warps of 64x64, double-buffered
// ---------------------------------------------------------------------------
__global__ void __launch_bounds__(128, 2) out_gemm(const float* __restrict__ bout,
                                                   float* __restrict__ out) {
    __shared__ union U {
        struct { uint32_t As[2][16][PADW]; uint32_t Bs[2][16][PADW]; } mm;
        float sbuf[128][129];
        __device__ U() {}
    } sh;
    __shared__ int   rowoff[128];
    __shared__ float bout_s[128];

    const int m0  = blockIdx.y * 128;
    const int n0  = blockIdx.x * 128;
    const int tid = threadIdx.x;

    rowoff[tid] = row_to_off(m0 + tid);
    bout_s[tid] = bout[n0 + tid];

    const int lane = tid & 31;
    const int wid  = tid >> 5;
    const int mb   = (wid & 1) * 64;
    const int nb   = (wid >> 1) * 64;
    const int tg   = lane >> 2;
    const int tq   = lane & 3;

    const uint32_t* arow = g_att32 + (size_t)(m0 + tid) * INNER;
    const uint32_t* brow = g_wout32 + n0 + tid;

    float d[4][8][4] = {};
    uint32_t a_reg[16], b_reg[16];

    #pragma unroll
    for (int i = 0; i < 4; i++)
        *(uint4*)&a_reg[4 * i] = *(const uint4*)(arow + 4 * i);
    #pragma unroll
    for (int i = 0; i < 16; i++) b_reg[i] = brow[i * DIM];
    #pragma unroll
    for (int i = 0; i < 16; i++) {
        sh.mm.As[0][i][tid] = a_reg[i];
        sh.mm.Bs[0][i][tid] = b_reg[i];
    }
    __syncthreads();

    for (int c = 0; c < 16; c++) {
        const int cur = c & 1;
        if (c < 15) {
            const int kb = (c + 1) * 16;
            #pragma unroll
            for (int i = 0; i < 4; i++)
                *(uint4*)&a_reg[4 * i] = *(const uint4*)(arow + kb + 4 * i);
            #pragma unroll
            for (int i = 0; i < 16; i++) b_reg[i] = brow[(kb + i) * DIM];
        }
        #pragma unroll
        for (int s = 0; s < 2; s++) {
            uint32_t a[4][4], b[8][2];
            #pragma unroll
            for (int am = 0; am < 4; am++) {
                int r = mb + am * 16 + tg;
                a[am][0] = sh.mm.As[cur][s * 8 + tq][r];
                a[am][1] = sh.mm.As[cur][s * 8 + tq][r + 8];
                a[am][2] = sh.mm.As[cur][s * 8 + tq + 4][r];
                a[am][3] = sh.mm.As[cur][s * 8 + tq + 4][r + 8];
            }
            #pragma unroll
            for (int an = 0; an < 8; an++) {
                int cc = nb + an * 8 + tg;
                b[an][0] = sh.mm.Bs[cur][s * 8 + tq][cc];
                b[an][1] = sh.mm.Bs[cur][s * 8 + tq + 4][cc];
            }
            #pragma unroll
            for (int am = 0; am < 4; am++)
                #pragma unroll
                for (int an = 0; an < 8; an++)
                    mma_tf32(d[am][an], a[am], b[an]);
        }
        if (c < 15) {
            const int nxt = cur ^ 1;
            #pragma unroll
            for (int i = 0; i < 16; i++) {
                sh.mm.As[nxt][i][tid] = a_reg[i];
                sh.mm.Bs[nxt][i][tid] = b_reg[i];
            }
        }
        __syncthreads();
    }

    // stage to sbuf (stride 129, conflict-free), then coalesced-ish scatter
    #pragma unroll
    for (int am = 0; am < 4; am++) {
        int r0 = mb + am * 16 + tg;
        #pragma unroll
        for (int an = 0; an < 8; an++) {
            int c = nb + an * 8 + 2 * tq;
            sh.sbuf[r0][c]     = d[am][an][0];
            sh.sbuf[r0][c + 1] = d[am][an][1];
            sh.sbuf[r0 + 8][c]     = d[am][an][2];
            sh.sbuf[r0 + 8][c + 1] = d[am][an][3];
        }
    }
    __syncthreads();

    #pragma unroll
    for (int it = 0; it < 128; it++) {
        int flat = it * 128 + tid;
        int m = flat & 127;
        int c = flat >> 7;
        out[rowoff[m] + (n0 + c) * SP] = sh.sbuf[m][c] + bout_s[c];
    }
}

// ---------------------------------------------------------------------------
extern "C" void kernel_launch(void* const* d_in, const int* in_sizes, int n_in,
                              void* d_out, int out_size) {
    const float* x    = (const float*)d_in[0];
    const float* pos  = (const float*)d_in[1];
    const float* wqkv = (const float*)d_in[2];
    const float* wout = (const float*)d_in[3];
    const float* bout = (const float*)d_in[4];

    float* out      = (float*)d_out;
    float* attn_out = out + (size_t)BATCH * DIM * SP;

    prep_w<<<256, 256>>>(wqkv, wout);

    dim3 g1(QKV_N / 128, M_TOTAL / 128);   // n fastest -> x reused in L2
    qkv_gemm<<<g1, 128>>>(x);

    attn_kernel<<<BATCH * NWIN * HEADS, 256>>>(pos, attn_out);

    dim3 g3(DIM / 128, M_TOTAL / 128);     // n fastest -> g_att reused in L2
    out_gemm<<<g3, 128>>>(bout, out);
}